// round 1
// baseline (speedup 1.0000x reference)
#include <cuda_runtime.h>

// ---------------------------------------------------------------------------
// ResBlock sparse-conv (Cylinder3D style), fp32 baseline using fma.rn.f32x2
// Pipeline:
//   y1 = lrelu(spconv(feats, map31, W1));           stats -> scale0/shift0 (g0,b0)
//   y2 = lrelu(spconv(BN0(y1), map13, W1_2));       stats -> scale1/shift1 (g0_2,b0_2)
//   y3 = lrelu(spconv(feats, map13, W2));           stats -> scale2/shift2 (g1,b1)
//   y4 = lrelu(spconv(BN2(y3), map31, W3));         stats -> scale3/shift3 (g2,b2)
//   resA = BN3(y4) + BN1(y2)                        -> d_out[M*128 ..]
//   resB = spconv(resA, map_pool, Wpool)            -> d_out[0 .. M*128)
// BN affine is fused into the NEXT conv's gather (empty taps stay exactly 0).
// ---------------------------------------------------------------------------

constexpr int CO   = 128;   // all convs have COUT=128
constexpr int TM   = 128;   // output rows per block
constexpr int TK   = 16;    // cin chunk
constexpr int MAXN = 300000;
constexpr int MAXB = (MAXN + TM - 1) / TM;   // 2344

__device__ float g_Y1[(size_t)MAXN * CO];
__device__ float g_Y2[(size_t)MAXN * CO];
__device__ float g_Y4[(size_t)MAXN * CO];
__device__ float g_part[(size_t)MAXB * 256];
__device__ float g_part2[64 * 256];
__device__ float g_scale[4 * CO];
__device__ float g_shift[4 * CO];

__device__ __forceinline__ unsigned long long pack2(float a) {
    unsigned long long r;
    asm("mov.b64 %0, {%1, %1};" : "=l"(r) : "f"(a));
    return r;
}
__device__ __forceinline__ void fma2(unsigned long long& d, unsigned long long a,
                                     unsigned long long b) {
    asm("fma.rn.f32x2 %0, %1, %2, %0;" : "+l"(d) : "l"(a), "l"(b));
}
__device__ __forceinline__ void unpack2(unsigned long long v, float& lo, float& hi) {
    asm("mov.b64 {%0, %1}, %2;" : "=f"(lo), "=f"(hi) : "l"(v));
}

// Gather-GEMM sparse conv. Block: 128 out rows x 128 out cols, 256 threads,
// 8x8 register micro-tile per thread, TK=16 cin chunk in smem.
// FUSEBN: apply per-cin scale/shift to gathered (valid) inputs.
// STATS:  apply LeakyReLU and emit per-block per-channel sum/sumsq partials.
template<int CIN, bool FUSEBN, bool STATS>
__global__ void __launch_bounds__(256, 2) spconv_kernel(
    const float* __restrict__ Fin, const int* __restrict__ kmap,
    int K, int M, const float* __restrict__ W,
    const float* __restrict__ inScale, const float* __restrict__ inShift,
    float* __restrict__ Out, float* __restrict__ partials)
{
    __shared__ float As[TK][TM + 4];     // transposed gathered input tile
    __shared__ float Bs[TK][CO];         // weight tile
    __shared__ int   sIdx[TM];
    __shared__ float sRed[256 * 16];     // stats reduction
    __shared__ float sSc[128], sSh[128];

    const int tid  = threadIdx.x;
    const int m0   = blockIdx.x * TM;
    const int tcol = tid & 15;           // cols: tcol*4+{0..3} and 64+tcol*4+{0..3}
    const int trow = tid >> 4;           // rows: trow*4+{0..3} and 64+trow*4+{0..3}

    if (FUSEBN) {
        if (tid < CIN) { sSc[tid] = inScale[tid]; sSh[tid] = inShift[tid]; }
    }

    unsigned long long acc[8][4];
#pragma unroll
    for (int r = 0; r < 8; ++r)
#pragma unroll
        for (int p = 0; p < 4; ++p) acc[r][p] = 0ull;

#pragma unroll 1
    for (int k = 0; k < K; ++k) {
        __syncthreads();                          // prior readers of sIdx done
        if (tid < TM) {
            int m = m0 + tid;
            sIdx[tid] = (m < M) ? kmap[(size_t)k * M + m] : -1;
        }
        __syncthreads();
#pragma unroll 1
        for (int c0 = 0; c0 < CIN; c0 += TK) {
            // ---- load phase (to registers) ----
            float4 va[2];
#pragma unroll
            for (int j = 0; j < 2; ++j) {
                int i   = tid + j * 256;          // 0..511 -> 128 rows x 4 float4
                int row = i >> 2;
                int cq  = (i & 3) << 2;
                int idx = sIdx[row];
                float4 v = make_float4(0.f, 0.f, 0.f, 0.f);
                if (idx >= 0) {
                    v = __ldg((const float4*)(Fin + (size_t)idx * CIN + (c0 + cq)));
                    if (FUSEBN) {
                        v.x = fmaf(v.x, sSc[c0 + cq + 0], sSh[c0 + cq + 0]);
                        v.y = fmaf(v.y, sSc[c0 + cq + 1], sSh[c0 + cq + 1]);
                        v.z = fmaf(v.z, sSc[c0 + cq + 2], sSh[c0 + cq + 2]);
                        v.w = fmaf(v.w, sSc[c0 + cq + 3], sSh[c0 + cq + 3]);
                    }
                }
                va[j] = v;
            }
            float4 vb[2];
#pragma unroll
            for (int j = 0; j < 2; ++j) {
                int i  = tid + j * 256;           // 16 rows x 32 float4
                int kk = i >> 5;
                int c4 = (i & 31) << 2;
                vb[j] = __ldg((const float4*)(W + ((size_t)k * CIN + (c0 + kk)) * CO + c4));
            }
            __syncthreads();                      // previous chunk compute done
            // ---- store phase ----
#pragma unroll
            for (int j = 0; j < 2; ++j) {
                int i   = tid + j * 256;
                int row = i >> 2;
                int cq  = (i & 3) << 2;
                As[cq + 0][row] = va[j].x;
                As[cq + 1][row] = va[j].y;
                As[cq + 2][row] = va[j].z;
                As[cq + 3][row] = va[j].w;
                int kk = i >> 5;
                int c4 = (i & 31) << 2;
                *(float4*)&Bs[kk][c4] = vb[j];
            }
            __syncthreads();
            // ---- compute phase ----
#pragma unroll
            for (int kk = 0; kk < TK; ++kk) {
                float4 a0 = *(const float4*)&As[kk][trow * 4];
                float4 a1 = *(const float4*)&As[kk][64 + trow * 4];
                ulonglong2 b0 = *(const ulonglong2*)&Bs[kk][tcol * 4];
                ulonglong2 b1 = *(const ulonglong2*)&Bs[kk][64 + tcol * 4];
                unsigned long long ap[8] = {pack2(a0.x), pack2(a0.y), pack2(a0.z), pack2(a0.w),
                                            pack2(a1.x), pack2(a1.y), pack2(a1.z), pack2(a1.w)};
                unsigned long long bp[4] = {b0.x, b0.y, b1.x, b1.y};
#pragma unroll
                for (int r = 0; r < 8; ++r)
#pragma unroll
                    for (int p = 0; p < 4; ++p) fma2(acc[r][p], ap[r], bp[p]);
            }
        }
    }

    // ---- epilogue: (lrelu) + store + (stats partials) ----
    float vs[8], vq[8];
#pragma unroll
    for (int c = 0; c < 8; ++c) { vs[c] = 0.f; vq[c] = 0.f; }

#pragma unroll
    for (int r = 0; r < 8; ++r) {
        int lr = (r < 4) ? (trow * 4 + r) : (64 + trow * 4 + (r - 4));
        int gr = m0 + lr;
        bool valid = gr < M;
        float v[8];
#pragma unroll
        for (int p = 0; p < 4; ++p) unpack2(acc[r][p], v[2 * p], v[2 * p + 1]);
        if (STATS) {
#pragma unroll
            for (int c = 0; c < 8; ++c) {
                float x = v[c];
                v[c] = (x >= 0.f) ? x : 0.01f * x;
            }
            if (valid) {
#pragma unroll
                for (int c = 0; c < 8; ++c) { vs[c] += v[c]; vq[c] += v[c] * v[c]; }
            }
        }
        if (valid) {
            float* orow = Out + (size_t)gr * CO;
            *(float4*)&orow[tcol * 4]      = make_float4(v[0], v[1], v[2], v[3]);
            *(float4*)&orow[64 + tcol * 4] = make_float4(v[4], v[5], v[6], v[7]);
        }
    }

    if (STATS) {
#pragma unroll
        for (int c = 0; c < 8; ++c) {
            sRed[tid * 16 + c]     = vs[c];
            sRed[tid * 16 + 8 + c] = vq[c];
        }
        __syncthreads();
        // thread u: channel c = u&127, stat = u>>7 (0=sum,1=sumsq)
        int c    = tid & 127;
        int stat = tid >> 7;
        int half = c >> 6;
        int cc   = c & 63;
        int tc   = cc >> 2;
        int sl   = half * 4 + (cc & 3) + stat * 8;
        float s = 0.f;
#pragma unroll
        for (int tr = 0; tr < 16; ++tr) s += sRed[(tr * 16 + tc) * 16 + sl];
        partials[(size_t)blockIdx.x * 256 + tid] = s;
    }
}

// Deterministic hierarchical stats reduction: 64 blocks x 256 threads (cols coalesced)
__global__ void reduce1_kernel(const float* __restrict__ part, int nb,
                               float* __restrict__ part2) {
    int rpb = (nb + 63) >> 6;
    int r0  = blockIdx.x * rpb;
    int r1  = min(nb, r0 + rpb);
    float s = 0.f;
    for (int r = r0; r < r1; ++r) s += part[(size_t)r * 256 + threadIdx.x];
    part2[blockIdx.x * 256 + threadIdx.x] = s;
}

__global__ void reduce2_kernel(const float* __restrict__ part2, float invn,
                               const float* __restrict__ g, const float* __restrict__ b,
                               float* __restrict__ scale, float* __restrict__ shift) {
    int c = threadIdx.x;   // 128
    float s = 0.f, q = 0.f;
#pragma unroll
    for (int j = 0; j < 64; ++j) {
        s += part2[j * 256 + c];
        q += part2[j * 256 + 128 + c];
    }
    float mean = s * invn;
    float var  = q * invn - mean * mean;
    float sc   = g[c] * rsqrtf(var + 1e-5f);
    scale[c] = sc;
    shift[c] = b[c] - mean * sc;
}

// resA = BN3(y4) + BN1(y2), vectorized float4
__global__ void add_bn_kernel(const float* __restrict__ y4, const float* __restrict__ y2,
                              const float* __restrict__ sc4, const float* __restrict__ sh4,
                              const float* __restrict__ sc2, const float* __restrict__ sh2,
                              float* __restrict__ out, int n4) {
    int i = blockIdx.x * blockDim.x + threadIdx.x;
    if (i >= n4) return;
    int cg = i & 31;   // 32 float4 groups per 128-ch row
    float4 a  = __ldg((const float4*)y4 + i);
    float4 c  = __ldg((const float4*)y2 + i);
    float4 s4 = __ldg((const float4*)sc4 + cg);
    float4 h4 = __ldg((const float4*)sh4 + cg);
    float4 s2 = __ldg((const float4*)sc2 + cg);
    float4 h2 = __ldg((const float4*)sh2 + cg);
    float4 o;
    o.x = fmaf(a.x, s4.x, h4.x) + fmaf(c.x, s2.x, h2.x);
    o.y = fmaf(a.y, s4.y, h4.y) + fmaf(c.y, s2.y, h2.y);
    o.z = fmaf(a.z, s4.z, h4.z) + fmaf(c.z, s2.z, h2.z);
    o.w = fmaf(a.w, s4.w, h4.w) + fmaf(c.w, s2.w, h2.w);
    ((float4*)out)[i] = o;
}

extern "C" void kernel_launch(void* const* d_in, const int* in_sizes, int n_in,
                              void* d_out, int out_size) {
    const float* feats = (const float*)d_in[0];
    const int*   map31 = (const int*)d_in[1];
    const int*   map13 = (const int*)d_in[2];
    const int*   mpool = (const int*)d_in[3];
    const float* W1    = (const float*)d_in[4];
    const float* W1_2  = (const float*)d_in[5];
    const float* W2    = (const float*)d_in[6];
    const float* W3    = (const float*)d_in[7];
    const float* Wp    = (const float*)d_in[8];
    const float* g0    = (const float*)d_in[9];
    const float* b0    = (const float*)d_in[10];
    const float* g0_2  = (const float*)d_in[11];
    const float* b0_2  = (const float*)d_in[12];
    const float* g1    = (const float*)d_in[13];
    const float* b1    = (const float*)d_in[14];
    const float* g2    = (const float*)d_in[15];
    const float* b2    = (const float*)d_in[16];

    int N = in_sizes[0] / 64;
    int M = in_sizes[3] / 27;

    float *Y1, *Y2, *Y4, *part, *part2, *scaleA, *shiftA;
    cudaGetSymbolAddress((void**)&Y1, g_Y1);
    cudaGetSymbolAddress((void**)&Y2, g_Y2);
    cudaGetSymbolAddress((void**)&Y4, g_Y4);
    cudaGetSymbolAddress((void**)&part, g_part);
    cudaGetSymbolAddress((void**)&part2, g_part2);
    cudaGetSymbolAddress((void**)&scaleA, g_scale);
    cudaGetSymbolAddress((void**)&shiftA, g_shift);

    float* resB = (float*)d_out;                       // [M,128]
    float* resA = (float*)d_out + (size_t)M * CO;      // [N,128]

    int nb = (N + TM - 1) / TM;
    int mb = (M + TM - 1) / TM;
    float invn = 1.0f / (float)N;

    // conv1 (3,1,3): feats -> y1, stats0
    spconv_kernel<64, false, true><<<nb, 256>>>(feats, map31, 9, N, W1,
                                                nullptr, nullptr, Y1, part);
    reduce1_kernel<<<64, 256>>>(part, nb, part2);
    reduce2_kernel<<<1, 128>>>(part2, invn, g0, b0, scaleA + 0, shiftA + 0);

    // conv1_2 (1,3,3): BN0(y1) -> y2, stats1
    spconv_kernel<128, true, true><<<nb, 256>>>(Y1, map13, 9, N, W1_2,
                                                scaleA + 0, shiftA + 0, Y2, part);
    reduce1_kernel<<<64, 256>>>(part, nb, part2);
    reduce2_kernel<<<1, 128>>>(part2, invn, g0_2, b0_2, scaleA + 128, shiftA + 128);

    // conv2 (1,3,3): feats -> y3 (reuse Y1 buffer), stats2
    spconv_kernel<64, false, true><<<nb, 256>>>(feats, map13, 9, N, W2,
                                                nullptr, nullptr, Y1, part);
    reduce1_kernel<<<64, 256>>>(part, nb, part2);
    reduce2_kernel<<<1, 128>>>(part2, invn, g1, b1, scaleA + 256, shiftA + 256);

    // conv3 (3,1,3): BN2(y3) -> y4, stats3
    spconv_kernel<128, true, true><<<nb, 256>>>(Y1, map31, 9, N, W3,
                                                scaleA + 256, shiftA + 256, Y4, part);
    reduce1_kernel<<<64, 256>>>(part, nb, part2);
    reduce2_kernel<<<1, 128>>>(part2, invn, g2, b2, scaleA + 384, shiftA + 384);

    // resA = BN3(y4) + BN1(y2)
    int n4 = N * (CO / 4);
    add_bn_kernel<<<(n4 + 255) / 256, 256>>>(Y4, Y2, scaleA + 384, shiftA + 384,
                                             scaleA + 128, shiftA + 128, resA, n4);

    // pool conv (3,3,3) stride (2,2,1): resA -> resB
    spconv_kernel<128, false, false><<<mb, 256>>>(resA, mpool, 27, M, Wp,
                                                  nullptr, nullptr, resB, nullptr);
}

// round 2
// speedup vs baseline: 4.1531x; 4.1531x over previous
#include <cuda_runtime.h>

// ---------------------------------------------------------------------------
// ResBlock sparse-conv, round 2: exploit tap sparsity (~5.4% voxel density).
//   submanifold convs: dense GEMM for the (always-valid, identity) center tap
//                      + compacted scatter-GEMM for the ~5.4%-hit other taps
//   pool conv:         zero-init + compacted scatter-GEMM over all 27 taps
// Convs store RAW outputs; LeakyReLU+BN is fused into the consumer's gather.
// BN batch stats via a dedicated memory-bound pass.
// ---------------------------------------------------------------------------

constexpr int CO   = 128;
constexpr int TM   = 128;
constexpr int TK   = 16;
constexpr int MAXN = 300000;
constexpr int MAXB = (MAXN + TM - 1) / TM;        // 2344
constexpr int STATS_GB = 2048;
constexpr int SCATTER_GRID = 304;

__device__ float g_Y1[(size_t)MAXN * CO];
__device__ float g_Y2[(size_t)MAXN * CO];
__device__ float g_Y4[(size_t)MAXN * CO];
__device__ float g_part[(size_t)MAXB * 256];
__device__ float g_part2[64 * 256];
__device__ float g_scale[4 * CO];
__device__ float g_shift[4 * CO];

__device__ int2 g_pairs31[(size_t)9 * MAXN];
__device__ int2 g_pairs13[(size_t)9 * MAXN];
__device__ int2 g_pairsP[(size_t)27 * MAXN];
__device__ int  g_cnt[64];                         // 0..8: map31, 16..24: map13, 32..58: pool
__device__ int  g_dirTap[110000];
__device__ int  g_dirBase[110000];
__device__ int  g_nt[4];

__device__ __forceinline__ unsigned long long pack2(float a) {
    unsigned long long r;
    asm("mov.b64 %0, {%1, %1};" : "=l"(r) : "f"(a));
    return r;
}
__device__ __forceinline__ void fma2(unsigned long long& d, unsigned long long a,
                                     unsigned long long b) {
    asm("fma.rn.f32x2 %0, %1, %2, %0;" : "+l"(d) : "l"(a), "l"(b));
}
__device__ __forceinline__ void unpack2(unsigned long long v, float& lo, float& hi) {
    asm("mov.b64 {%0, %1}, %2;" : "=f"(lo), "=f"(hi) : "l"(v));
}
__device__ __forceinline__ void redadd4(float* p, float a, float b, float c, float d) {
    asm volatile("red.global.add.v4.f32 [%0], {%1,%2,%3,%4};"
                 :: "l"(p), "f"(a), "f"(b), "f"(c), "f"(d) : "memory");
}
__device__ __forceinline__ float lrelu(float x) { return (x >= 0.f) ? x : 0.01f * x; }

// ---------------------------------------------------------------------------
// Compaction: append valid (out_row, in_row) pairs per tap segment.
// ---------------------------------------------------------------------------
__global__ void compact_kernel(const int* __restrict__ kmap, int K, int M, int center,
                               int2* __restrict__ pairs, int cap, int* __restrict__ cnt) {
    int i = blockIdx.x * 256 + threadIdx.x;
    if (i >= K * M) return;
    int k = i / M;
    if (k == center) return;
    int idx = kmap[i];
    if (idx >= 0) {
        int pos = atomicAdd(&cnt[k], 1);
        pairs[(size_t)k * cap + pos] = make_int2(i - k * M, idx);
    }
}

__global__ void pad_kernel(const int* __restrict__ cnt, int2* __restrict__ pairs, int cap) {
    int k = blockIdx.x;
    int c = cnt[k];
    int e = ((c + TM - 1) / TM) * TM;
    for (int j = c + threadIdx.x; j < e; j += blockDim.x)
        pairs[(size_t)k * cap + j] = make_int2(-1, 0);
}

__global__ void build_dir_kernel(const int* __restrict__ cnt, int K, int cap,
                                 int* __restrict__ tileTap, int* __restrict__ tileBase,
                                 int* __restrict__ ntOut) {
    __shared__ int ntk[32], off[32];
    if (threadIdx.x == 0) {
        int t = 0;
        for (int k = 0; k < K; ++k) {
            off[k] = t;
            ntk[k] = (cnt[k] + TM - 1) / TM;
            t += ntk[k];
        }
        *ntOut = t;
    }
    __syncthreads();
    for (int k = 0; k < K; ++k)
        for (int j = threadIdx.x; j < ntk[k]; j += blockDim.x) {
            tileTap[off[k] + j]  = k;
            tileBase[off[k] + j] = k * cap + j * TM;
        }
}

// ---------------------------------------------------------------------------
// Dense center-tap GEMM: Out[m] = T(Fin[m]) @ Wc   (T = lrelu+BN if FUSE)
// ---------------------------------------------------------------------------
template<int CIN, bool FUSE>
__global__ void __launch_bounds__(256, 2) center_kernel(
    const float* __restrict__ Fin, const float* __restrict__ Wc, int M,
    const float* __restrict__ inScale, const float* __restrict__ inShift,
    float* __restrict__ Out)
{
    __shared__ float As[TK][TM + 4];
    __shared__ float Bs[TK][CO];
    __shared__ float sSc[128], sSh[128];

    const int tid  = threadIdx.x;
    const int m0   = blockIdx.x * TM;
    const int tcol = tid & 15;
    const int trow = tid >> 4;

    if (FUSE && tid < CIN) { sSc[tid] = inScale[tid]; sSh[tid] = inShift[tid]; }
    __syncthreads();

    unsigned long long acc[8][4];
#pragma unroll
    for (int r = 0; r < 8; ++r)
#pragma unroll
        for (int p = 0; p < 4; ++p) acc[r][p] = 0ull;

#pragma unroll 1
    for (int c0 = 0; c0 < CIN; c0 += TK) {
        float4 va[2];
#pragma unroll
        for (int j = 0; j < 2; ++j) {
            int i   = tid + j * 256;
            int row = i >> 2;
            int cq  = (i & 3) << 2;
            int m   = m0 + row;
            float4 v = make_float4(0.f, 0.f, 0.f, 0.f);
            if (m < M) {
                v = __ldg((const float4*)(Fin + (size_t)m * CIN + (c0 + cq)));
                if (FUSE) {
                    v.x = fmaf(lrelu(v.x), sSc[c0 + cq + 0], sSh[c0 + cq + 0]);
                    v.y = fmaf(lrelu(v.y), sSc[c0 + cq + 1], sSh[c0 + cq + 1]);
                    v.z = fmaf(lrelu(v.z), sSc[c0 + cq + 2], sSh[c0 + cq + 2]);
                    v.w = fmaf(lrelu(v.w), sSc[c0 + cq + 3], sSh[c0 + cq + 3]);
                }
            }
            va[j] = v;
        }
        float4 vb[2];
#pragma unroll
        for (int j = 0; j < 2; ++j) {
            int i  = tid + j * 256;
            int kk = i >> 5;
            int c4 = (i & 31) << 2;
            vb[j]  = __ldg((const float4*)(Wc + (size_t)(c0 + kk) * CO + c4));
        }
        __syncthreads();
#pragma unroll
        for (int j = 0; j < 2; ++j) {
            int i   = tid + j * 256;
            int row = i >> 2;
            int cq  = (i & 3) << 2;
            As[cq + 0][row] = va[j].x;
            As[cq + 1][row] = va[j].y;
            As[cq + 2][row] = va[j].z;
            As[cq + 3][row] = va[j].w;
            int kk = i >> 5;
            int c4 = (i & 31) << 2;
            *(float4*)&Bs[kk][c4] = vb[j];
        }
        __syncthreads();
#pragma unroll
        for (int kk = 0; kk < TK; ++kk) {
            float4 a0 = *(const float4*)&As[kk][trow * 4];
            float4 a1 = *(const float4*)&As[kk][64 + trow * 4];
            ulonglong2 b0 = *(const ulonglong2*)&Bs[kk][tcol * 4];
            ulonglong2 b1 = *(const ulonglong2*)&Bs[kk][64 + tcol * 4];
            unsigned long long ap[8] = {pack2(a0.x), pack2(a0.y), pack2(a0.z), pack2(a0.w),
                                        pack2(a1.x), pack2(a1.y), pack2(a1.z), pack2(a1.w)};
            unsigned long long bp[4] = {b0.x, b0.y, b1.x, b1.y};
#pragma unroll
            for (int r = 0; r < 8; ++r)
#pragma unroll
                for (int p = 0; p < 4; ++p) fma2(acc[r][p], ap[r], bp[p]);
        }
    }

#pragma unroll
    for (int r = 0; r < 8; ++r) {
        int lr = (r < 4) ? (trow * 4 + r) : (64 + trow * 4 + (r - 4));
        int gr = m0 + lr;
        if (gr < M) {
            float v[8];
#pragma unroll
            for (int p = 0; p < 4; ++p) unpack2(acc[r][p], v[2 * p], v[2 * p + 1]);
            float* orow = Out + (size_t)gr * CO;
            *(float4*)&orow[tcol * 4]      = make_float4(v[0], v[1], v[2], v[3]);
            *(float4*)&orow[64 + tcol * 4] = make_float4(v[4], v[5], v[6], v[7]);
        }
    }
}

// ---------------------------------------------------------------------------
// Scatter-GEMM over compacted tap tiles; epilogue = red.global.add.v4.f32
// ---------------------------------------------------------------------------
template<int CIN, bool FUSE>
__global__ void __launch_bounds__(256, 2) scatter_kernel(
    const float* __restrict__ Fin, const float* __restrict__ W,
    const int* __restrict__ tileTap, const int* __restrict__ tileBase,
    const int* __restrict__ ntPtr, const int2* __restrict__ pairs,
    const float* __restrict__ inScale, const float* __restrict__ inShift,
    float* __restrict__ Out)
{
    __shared__ float As[TK][TM + 4];
    __shared__ float Bs[TK][CO];
    __shared__ int   sM[TM], sI[TM];
    __shared__ float sSc[128], sSh[128];

    const int tid  = threadIdx.x;
    const int tcol = tid & 15;
    const int trow = tid >> 4;

    if (FUSE && tid < CIN) { sSc[tid] = inScale[tid]; sSh[tid] = inShift[tid]; }
    const int nTiles = __ldg(ntPtr);

    for (int t = blockIdx.x; t < nTiles; t += gridDim.x) {
        __syncthreads();
        const int k    = tileTap[t];
        const int base = tileBase[t];
        if (tid < TM) {
            int2 pr = pairs[(size_t)base + tid];
            sM[tid] = pr.x;
            sI[tid] = pr.y;
        }
        __syncthreads();
        const float* Wk = W + (size_t)k * CIN * CO;

        unsigned long long acc[8][4];
#pragma unroll
        for (int r = 0; r < 8; ++r)
#pragma unroll
            for (int p = 0; p < 4; ++p) acc[r][p] = 0ull;

#pragma unroll 1
        for (int c0 = 0; c0 < CIN; c0 += TK) {
            float4 va[2];
#pragma unroll
            for (int j = 0; j < 2; ++j) {
                int i   = tid + j * 256;
                int row = i >> 2;
                int cq  = (i & 3) << 2;
                int idx = sI[row];
                float4 v = __ldg((const float4*)(Fin + (size_t)idx * CIN + (c0 + cq)));
                if (FUSE) {
                    v.x = fmaf(lrelu(v.x), sSc[c0 + cq + 0], sSh[c0 + cq + 0]);
                    v.y = fmaf(lrelu(v.y), sSc[c0 + cq + 1], sSh[c0 + cq + 1]);
                    v.z = fmaf(lrelu(v.z), sSc[c0 + cq + 2], sSh[c0 + cq + 2]);
                    v.w = fmaf(lrelu(v.w), sSc[c0 + cq + 3], sSh[c0 + cq + 3]);
                }
                va[j] = v;
            }
            float4 vb[2];
#pragma unroll
            for (int j = 0; j < 2; ++j) {
                int i  = tid + j * 256;
                int kk = i >> 5;
                int c4 = (i & 31) << 2;
                vb[j]  = __ldg((const float4*)(Wk + (size_t)(c0 + kk) * CO + c4));
            }
            __syncthreads();
#pragma unroll
            for (int j = 0; j < 2; ++j) {
                int i   = tid + j * 256;
                int row = i >> 2;
                int cq  = (i & 3) << 2;
                As[cq + 0][row] = va[j].x;
                As[cq + 1][row] = va[j].y;
                As[cq + 2][row] = va[j].z;
                As[cq + 3][row] = va[j].w;
                int kk = i >> 5;
                int c4 = (i & 31) << 2;
                *(float4*)&Bs[kk][c4] = vb[j];
            }
            __syncthreads();
#pragma unroll
            for (int kk = 0; kk < TK; ++kk) {
                float4 a0 = *(const float4*)&As[kk][trow * 4];
                float4 a1 = *(const float4*)&As[kk][64 + trow * 4];
                ulonglong2 b0 = *(const ulonglong2*)&Bs[kk][tcol * 4];
                ulonglong2 b1 = *(const ulonglong2*)&Bs[kk][64 + tcol * 4];
                unsigned long long ap[8] = {pack2(a0.x), pack2(a0.y), pack2(a0.z), pack2(a0.w),
                                            pack2(a1.x), pack2(a1.y), pack2(a1.z), pack2(a1.w)};
                unsigned long long bp[4] = {b0.x, b0.y, b1.x, b1.y};
#pragma unroll
                for (int r = 0; r < 8; ++r)
#pragma unroll
                    for (int p = 0; p < 4; ++p) fma2(acc[r][p], ap[r], bp[p]);
            }
        }

#pragma unroll
        for (int r = 0; r < 8; ++r) {
            int lr = (r < 4) ? (trow * 4 + r) : (64 + trow * 4 + (r - 4));
            int m  = sM[lr];
            if (m >= 0) {
                float v[8];
#pragma unroll
                for (int p = 0; p < 4; ++p) unpack2(acc[r][p], v[2 * p], v[2 * p + 1]);
                float* orow = Out + (size_t)m * CO;
                redadd4(orow + tcol * 4,      v[0], v[1], v[2], v[3]);
                redadd4(orow + 64 + tcol * 4, v[4], v[5], v[6], v[7]);
            }
        }
    }
}

// ---------------------------------------------------------------------------
// BN stats on raw conv output (applies lrelu): per-block partial sum/sumsq.
// ---------------------------------------------------------------------------
__global__ void stats_kernel(const float* __restrict__ Y, int N, float* __restrict__ part) {
    int c    = threadIdx.x & 127;
    int half = threadIdx.x >> 7;
    int rows = (N + gridDim.x - 1) / gridDim.x;
    int r0   = blockIdx.x * rows;
    int r1   = min(N, r0 + rows);
    float s = 0.f, q = 0.f;
    for (int r = r0 + half; r < r1; r += 2) {
        float x = lrelu(__ldg(&Y[(size_t)r * 128 + c]));
        s += x; q += x * x;
    }
    __shared__ float sh[256];
    sh[threadIdx.x] = s; __syncthreads();
    if (half == 0) part[(size_t)blockIdx.x * 256 + c] = sh[c] + sh[128 + c];
    __syncthreads();
    sh[threadIdx.x] = q; __syncthreads();
    if (half == 0) part[(size_t)blockIdx.x * 256 + 128 + c] = sh[c] + sh[128 + c];
}

__global__ void reduce1_kernel(const float* __restrict__ part, int nb,
                               float* __restrict__ part2) {
    int rpb = (nb + 63) >> 6;
    int r0  = blockIdx.x * rpb;
    int r1  = min(nb, r0 + rpb);
    float s = 0.f;
    for (int r = r0; r < r1; ++r) s += part[(size_t)r * 256 + threadIdx.x];
    part2[blockIdx.x * 256 + threadIdx.x] = s;
}

__global__ void reduce2_kernel(const float* __restrict__ part2, float invn,
                               const float* __restrict__ g, const float* __restrict__ b,
                               float* __restrict__ scale, float* __restrict__ shift) {
    int c = threadIdx.x;
    float s = 0.f, q = 0.f;
#pragma unroll
    for (int j = 0; j < 64; ++j) {
        s += part2[j * 256 + c];
        q += part2[j * 256 + 128 + c];
    }
    float mean = s * invn;
    float var  = q * invn - mean * mean;
    float sc   = g[c] * rsqrtf(var + 1e-5f);
    scale[c] = sc;
    shift[c] = b[c] - mean * sc;
}

// resA = BN3(lrelu(y4)) + BN1(lrelu(y2))
__global__ void add_bn_kernel(const float* __restrict__ y4, const float* __restrict__ y2,
                              const float* __restrict__ sc4, const float* __restrict__ sh4,
                              const float* __restrict__ sc2, const float* __restrict__ sh2,
                              float* __restrict__ out, int n4) {
    int i = blockIdx.x * blockDim.x + threadIdx.x;
    if (i >= n4) return;
    int cg = i & 31;
    float4 a  = __ldg((const float4*)y4 + i);
    float4 c  = __ldg((const float4*)y2 + i);
    float4 s4 = __ldg((const float4*)sc4 + cg);
    float4 h4 = __ldg((const float4*)sh4 + cg);
    float4 s2 = __ldg((const float4*)sc2 + cg);
    float4 h2 = __ldg((const float4*)sh2 + cg);
    float4 o;
    o.x = fmaf(lrelu(a.x), s4.x, h4.x) + fmaf(lrelu(c.x), s2.x, h2.x);
    o.y = fmaf(lrelu(a.y), s4.y, h4.y) + fmaf(lrelu(c.y), s2.y, h2.y);
    o.z = fmaf(lrelu(a.z), s4.z, h4.z) + fmaf(lrelu(c.z), s2.z, h2.z);
    o.w = fmaf(lrelu(a.w), s4.w, h4.w) + fmaf(lrelu(c.w), s2.w, h2.w);
    ((float4*)out)[i] = o;
}

extern "C" void kernel_launch(void* const* d_in, const int* in_sizes, int n_in,
                              void* d_out, int out_size) {
    const float* feats = (const float*)d_in[0];
    const int*   map31 = (const int*)d_in[1];
    const int*   map13 = (const int*)d_in[2];
    const int*   mpool = (const int*)d_in[3];
    const float* W1    = (const float*)d_in[4];
    const float* W1_2  = (const float*)d_in[5];
    const float* W2    = (const float*)d_in[6];
    const float* W3    = (const float*)d_in[7];
    const float* Wp    = (const float*)d_in[8];
    const float* g0    = (const float*)d_in[9];
    const float* b0    = (const float*)d_in[10];
    const float* g0_2  = (const float*)d_in[11];
    const float* b0_2  = (const float*)d_in[12];
    const float* g1    = (const float*)d_in[13];
    const float* b1    = (const float*)d_in[14];
    const float* g2    = (const float*)d_in[15];
    const float* b2    = (const float*)d_in[16];

    int N = in_sizes[0] / 64;
    int M = in_sizes[3] / 27;

    float *Y1, *Y2, *Y4, *part, *part2, *scaleA, *shiftA;
    int2 *p31, *p13, *pP;
    int  *cnt, *dTap, *dBase, *nt;
    cudaGetSymbolAddress((void**)&Y1, g_Y1);
    cudaGetSymbolAddress((void**)&Y2, g_Y2);
    cudaGetSymbolAddress((void**)&Y4, g_Y4);
    cudaGetSymbolAddress((void**)&part, g_part);
    cudaGetSymbolAddress((void**)&part2, g_part2);
    cudaGetSymbolAddress((void**)&scaleA, g_scale);
    cudaGetSymbolAddress((void**)&shiftA, g_shift);
    cudaGetSymbolAddress((void**)&p31, g_pairs31);
    cudaGetSymbolAddress((void**)&p13, g_pairs13);
    cudaGetSymbolAddress((void**)&pP,  g_pairsP);
    cudaGetSymbolAddress((void**)&cnt, g_cnt);
    cudaGetSymbolAddress((void**)&dTap, g_dirTap);
    cudaGetSymbolAddress((void**)&dBase, g_dirBase);
    cudaGetSymbolAddress((void**)&nt, g_nt);

    float* resB = (float*)d_out;
    float* resA = (float*)d_out + (size_t)M * CO;

    int nb = (N + TM - 1) / TM;
    float invn = 1.0f / (float)N;

    // tile directory regions: map31 at 0, map13 at 20000, pool at 40000
    int* dTap31 = dTap;          int* dBase31 = dBase;
    int* dTap13 = dTap + 20000;  int* dBase13 = dBase + 20000;
    int* dTapP  = dTap + 40000;  int* dBaseP  = dBase + 40000;

    // ---- one-time compaction of the three maps ----
    cudaMemsetAsync(cnt, 0, 64 * sizeof(int));
    compact_kernel<<<(9 * N + 255) / 256, 256>>>(map31, 9, N, 4, p31, N, cnt);
    compact_kernel<<<(9 * N + 255) / 256, 256>>>(map13, 9, N, 4, p13, N, cnt + 16);
    compact_kernel<<<(27 * M + 255) / 256, 256>>>(mpool, 27, M, -1, pP, M, cnt + 32);
    pad_kernel<<<9, 128>>>(cnt, p31, N);
    pad_kernel<<<9, 128>>>(cnt + 16, p13, N);
    pad_kernel<<<27, 128>>>(cnt + 32, pP, M);
    build_dir_kernel<<<1, 256>>>(cnt, 9, N, dTap31, dBase31, nt + 0);
    build_dir_kernel<<<1, 256>>>(cnt + 16, 9, N, dTap13, dBase13, nt + 1);
    build_dir_kernel<<<1, 256>>>(cnt + 32, 27, M, dTapP, dBaseP, nt + 2);

    // ---- conv1 (3,1,3): feats -> Y1 (raw) ----
    center_kernel<64, false><<<nb, 256>>>(feats, W1 + (size_t)4 * 64 * CO, N,
                                          nullptr, nullptr, Y1);
    scatter_kernel<64, false><<<SCATTER_GRID, 256>>>(feats, W1, dTap31, dBase31, nt + 0,
                                                     p31, nullptr, nullptr, Y1);
    stats_kernel<<<STATS_GB, 256>>>(Y1, N, part);
    reduce1_kernel<<<64, 256>>>(part, STATS_GB, part2);
    reduce2_kernel<<<1, 128>>>(part2, invn, g0, b0, scaleA + 0, shiftA + 0);

    // ---- conv1_2 (1,3,3): BN0(lrelu(Y1)) -> Y2 (raw) ----
    center_kernel<128, true><<<nb, 256>>>(Y1, W1_2 + (size_t)4 * 128 * CO, N,
                                          scaleA + 0, shiftA + 0, Y2);
    scatter_kernel<128, true><<<SCATTER_GRID, 256>>>(Y1, W1_2, dTap13, dBase13, nt + 1,
                                                     p13, scaleA + 0, shiftA + 0, Y2);
    stats_kernel<<<STATS_GB, 256>>>(Y2, N, part);
    reduce1_kernel<<<64, 256>>>(part, STATS_GB, part2);
    reduce2_kernel<<<1, 128>>>(part2, invn, g0_2, b0_2, scaleA + 128, shiftA + 128);

    // ---- conv2 (1,3,3): feats -> Y3 (reuse Y1) ----
    center_kernel<64, false><<<nb, 256>>>(feats, W2 + (size_t)4 * 64 * CO, N,
                                          nullptr, nullptr, Y1);
    scatter_kernel<64, false><<<SCATTER_GRID, 256>>>(feats, W2, dTap13, dBase13, nt + 1,
                                                     p13, nullptr, nullptr, Y1);
    stats_kernel<<<STATS_GB, 256>>>(Y1, N, part);
    reduce1_kernel<<<64, 256>>>(part, STATS_GB, part2);
    reduce2_kernel<<<1, 128>>>(part2, invn, g1, b1, scaleA + 256, shiftA + 256);

    // ---- conv3 (3,1,3): BN2(lrelu(Y3)) -> Y4 (raw) ----
    center_kernel<128, true><<<nb, 256>>>(Y1, W3 + (size_t)4 * 128 * CO, N,
                                          scaleA + 256, shiftA + 256, Y4);
    scatter_kernel<128, true><<<SCATTER_GRID, 256>>>(Y1, W3, dTap31, dBase31, nt + 0,
                                                     p31, scaleA + 256, shiftA + 256, Y4);
    stats_kernel<<<STATS_GB, 256>>>(Y4, N, part);
    reduce1_kernel<<<64, 256>>>(part, STATS_GB, part2);
    reduce2_kernel<<<1, 128>>>(part2, invn, g2, b2, scaleA + 384, shiftA + 384);

    // ---- resA = BN3(lrelu(Y4)) + BN1(lrelu(Y2)) ----
    int n4 = N * (CO / 4);
    add_bn_kernel<<<(n4 + 255) / 256, 256>>>(Y4, Y2, scaleA + 384, shiftA + 384,
                                             scaleA + 128, shiftA + 128, resA, n4);

    // ---- pool conv (3,3,3)/(2,2,1): resA -> resB ----
    cudaMemsetAsync(resB, 0, (size_t)M * CO * sizeof(float));
    scatter_kernel<128, false><<<SCATTER_GRID, 256>>>(resA, Wp, dTapP, dBaseP, nt + 2,
                                                      pP, nullptr, nullptr, resB);
}

// round 3
// speedup vs baseline: 4.1799x; 1.0064x over previous
#include <cuda_runtime.h>

// ---------------------------------------------------------------------------
// ResBlock sparse-conv, round 2: exploit tap sparsity (~5.4% voxel density).
//   submanifold convs: dense GEMM for the (always-valid, identity) center tap
//                      + compacted scatter-GEMM for the ~5.4%-hit other taps
//   pool conv:         zero-init + compacted scatter-GEMM over all 27 taps
// Convs store RAW outputs; LeakyReLU+BN is fused into the consumer's gather.
// BN batch stats via a dedicated memory-bound pass.
// ---------------------------------------------------------------------------

constexpr int CO   = 128;
constexpr int TM   = 128;
constexpr int TK   = 16;
constexpr int MAXN = 300000;
constexpr int MAXB = (MAXN + TM - 1) / TM;        // 2344
constexpr int STATS_GB = 2048;
constexpr int SCATTER_GRID = 304;

__device__ float g_Y1[(size_t)MAXN * CO];
__device__ float g_Y2[(size_t)MAXN * CO];
__device__ float g_Y4[(size_t)MAXN * CO];
__device__ float g_part[(size_t)MAXB * 256];
__device__ float g_part2[64 * 256];
__device__ float g_scale[4 * CO];
__device__ float g_shift[4 * CO];

__device__ int2 g_pairs31[(size_t)9 * MAXN];
__device__ int2 g_pairs13[(size_t)9 * MAXN];
__device__ int2 g_pairsP[(size_t)27 * MAXN];
__device__ int  g_cnt[64];                         // 0..8: map31, 16..24: map13, 32..58: pool
__device__ int  g_dirTap[110000];
__device__ int  g_dirBase[110000];
__device__ int  g_nt[4];

__device__ __forceinline__ unsigned long long pack2(float a) {
    unsigned long long r;
    asm("mov.b64 %0, {%1, %1};" : "=l"(r) : "f"(a));
    return r;
}
__device__ __forceinline__ void fma2(unsigned long long& d, unsigned long long a,
                                     unsigned long long b) {
    asm("fma.rn.f32x2 %0, %1, %2, %0;" : "+l"(d) : "l"(a), "l"(b));
}
__device__ __forceinline__ void unpack2(unsigned long long v, float& lo, float& hi) {
    asm("mov.b64 {%0, %1}, %2;" : "=f"(lo), "=f"(hi) : "l"(v));
}
__device__ __forceinline__ void redadd4(float* p, float a, float b, float c, float d) {
    asm volatile("red.global.add.v4.f32 [%0], {%1,%2,%3,%4};"
                 :: "l"(p), "f"(a), "f"(b), "f"(c), "f"(d) : "memory");
}
__device__ __forceinline__ float lrelu(float x) { return (x >= 0.f) ? x : 0.01f * x; }

// ---------------------------------------------------------------------------
// Compaction: append valid (out_row, in_row) pairs per tap segment.
// ---------------------------------------------------------------------------
__global__ void compact_kernel(const int* __restrict__ kmap, int K, int M, int center,
                               int2* __restrict__ pairs, int cap, int* __restrict__ cnt) {
    int i = blockIdx.x * 256 + threadIdx.x;
    if (i >= K * M) return;
    int k = i / M;
    if (k == center) return;
    int idx = kmap[i];
    if (idx >= 0) {
        int pos = atomicAdd(&cnt[k], 1);
        pairs[(size_t)k * cap + pos] = make_int2(i - k * M, idx);
    }
}

__global__ void pad_kernel(const int* __restrict__ cnt, int2* __restrict__ pairs, int cap) {
    int k = blockIdx.x;
    int c = cnt[k];
    int e = ((c + TM - 1) / TM) * TM;
    for (int j = c + threadIdx.x; j < e; j += blockDim.x)
        pairs[(size_t)k * cap + j] = make_int2(-1, 0);
}

__global__ void build_dir_kernel(const int* __restrict__ cnt, int K, int cap,
                                 int* __restrict__ tileTap, int* __restrict__ tileBase,
                                 int* __restrict__ ntOut) {
    __shared__ int ntk[32], off[32];
    if (threadIdx.x == 0) {
        int t = 0;
        for (int k = 0; k < K; ++k) {
            off[k] = t;
            ntk[k] = (cnt[k] + TM - 1) / TM;
            t += ntk[k];
        }
        *ntOut = t;
    }
    __syncthreads();
    for (int k = 0; k < K; ++k)
        for (int j = threadIdx.x; j < ntk[k]; j += blockDim.x) {
            tileTap[off[k] + j]  = k;
            tileBase[off[k] + j] = k * cap + j * TM;
        }
}

// ---------------------------------------------------------------------------
// Dense center-tap GEMM: Out[m] = T(Fin[m]) @ Wc   (T = lrelu+BN if FUSE)
// ---------------------------------------------------------------------------
template<int CIN, bool FUSE>
__global__ void __launch_bounds__(256, 2) center_kernel(
    const float* __restrict__ Fin, const float* __restrict__ Wc, int M,
    const float* __restrict__ inScale, const float* __restrict__ inShift,
    float* __restrict__ Out)
{
    __shared__ float As[TK][TM + 4];
    __shared__ float Bs[TK][CO];
    __shared__ float sSc[128], sSh[128];

    const int tid  = threadIdx.x;
    const int m0   = blockIdx.x * TM;
    const int tcol = tid & 15;
    const int trow = tid >> 4;

    if (FUSE && tid < CIN) { sSc[tid] = inScale[tid]; sSh[tid] = inShift[tid]; }
    __syncthreads();

    unsigned long long acc[8][4];
#pragma unroll
    for (int r = 0; r < 8; ++r)
#pragma unroll
        for (int p = 0; p < 4; ++p) acc[r][p] = 0ull;

#pragma unroll 1
    for (int c0 = 0; c0 < CIN; c0 += TK) {
        float4 va[2];
#pragma unroll
        for (int j = 0; j < 2; ++j) {
            int i   = tid + j * 256;
            int row = i >> 2;
            int cq  = (i & 3) << 2;
            int m   = m0 + row;
            float4 v = make_float4(0.f, 0.f, 0.f, 0.f);
            if (m < M) {
                v = __ldg((const float4*)(Fin + (size_t)m * CIN + (c0 + cq)));
                if (FUSE) {
                    v.x = fmaf(lrelu(v.x), sSc[c0 + cq + 0], sSh[c0 + cq + 0]);
                    v.y = fmaf(lrelu(v.y), sSc[c0 + cq + 1], sSh[c0 + cq + 1]);
                    v.z = fmaf(lrelu(v.z), sSc[c0 + cq + 2], sSh[c0 + cq + 2]);
                    v.w = fmaf(lrelu(v.w), sSc[c0 + cq + 3], sSh[c0 + cq + 3]);
                }
            }
            va[j] = v;
        }
        float4 vb[2];
#pragma unroll
        for (int j = 0; j < 2; ++j) {
            int i  = tid + j * 256;
            int kk = i >> 5;
            int c4 = (i & 31) << 2;
            vb[j]  = __ldg((const float4*)(Wc + (size_t)(c0 + kk) * CO + c4));
        }
        __syncthreads();
#pragma unroll
        for (int j = 0; j < 2; ++j) {
            int i   = tid + j * 256;
            int row = i >> 2;
            int cq  = (i & 3) << 2;
            As[cq + 0][row] = va[j].x;
            As[cq + 1][row] = va[j].y;
            As[cq + 2][row] = va[j].z;
            As[cq + 3][row] = va[j].w;
            int kk = i >> 5;
            int c4 = (i & 31) << 2;
            *(float4*)&Bs[kk][c4] = vb[j];
        }
        __syncthreads();
#pragma unroll
        for (int kk = 0; kk < TK; ++kk) {
            float4 a0 = *(const float4*)&As[kk][trow * 4];
            float4 a1 = *(const float4*)&As[kk][64 + trow * 4];
            ulonglong2 b0 = *(const ulonglong2*)&Bs[kk][tcol * 4];
            ulonglong2 b1 = *(const ulonglong2*)&Bs[kk][64 + tcol * 4];
            unsigned long long ap[8] = {pack2(a0.x), pack2(a0.y), pack2(a0.z), pack2(a0.w),
                                        pack2(a1.x), pack2(a1.y), pack2(a1.z), pack2(a1.w)};
            unsigned long long bp[4] = {b0.x, b0.y, b1.x, b1.y};
#pragma unroll
            for (int r = 0; r < 8; ++r)
#pragma unroll
                for (int p = 0; p < 4; ++p) fma2(acc[r][p], ap[r], bp[p]);
        }
    }

#pragma unroll
    for (int r = 0; r < 8; ++r) {
        int lr = (r < 4) ? (trow * 4 + r) : (64 + trow * 4 + (r - 4));
        int gr = m0 + lr;
        if (gr < M) {
            float v[8];
#pragma unroll
            for (int p = 0; p < 4; ++p) unpack2(acc[r][p], v[2 * p], v[2 * p + 1]);
            float* orow = Out + (size_t)gr * CO;
            *(float4*)&orow[tcol * 4]      = make_float4(v[0], v[1], v[2], v[3]);
            *(float4*)&orow[64 + tcol * 4] = make_float4(v[4], v[5], v[6], v[7]);
        }
    }
}

// ---------------------------------------------------------------------------
// Scatter-GEMM over compacted tap tiles; epilogue = red.global.add.v4.f32
// ---------------------------------------------------------------------------
template<int CIN, bool FUSE>
__global__ void __launch_bounds__(256, 2) scatter_kernel(
    const float* __restrict__ Fin, const float* __restrict__ W,
    const int* __restrict__ tileTap, const int* __restrict__ tileBase,
    const int* __restrict__ ntPtr, const int2* __restrict__ pairs,
    const float* __restrict__ inScale, const float* __restrict__ inShift,
    float* __restrict__ Out)
{
    __shared__ float As[TK][TM + 4];
    __shared__ float Bs[TK][CO];
    __shared__ int   sM[TM], sI[TM];
    __shared__ float sSc[128], sSh[128];

    const int tid  = threadIdx.x;
    const int tcol = tid & 15;
    const int trow = tid >> 4;

    if (FUSE && tid < CIN) { sSc[tid] = inScale[tid]; sSh[tid] = inShift[tid]; }
    const int nTiles = __ldg(ntPtr);

    for (int t = blockIdx.x; t < nTiles; t += gridDim.x) {
        __syncthreads();
        const int k    = tileTap[t];
        const int base = tileBase[t];
        if (tid < TM) {
            int2 pr = pairs[(size_t)base + tid];
            sM[tid] = pr.x;
            sI[tid] = pr.y;
        }
        __syncthreads();
        const float* Wk = W + (size_t)k * CIN * CO;

        unsigned long long acc[8][4];
#pragma unroll
        for (int r = 0; r < 8; ++r)
#pragma unroll
            for (int p = 0; p < 4; ++p) acc[r][p] = 0ull;

#pragma unroll 1
        for (int c0 = 0; c0 < CIN; c0 += TK) {
            float4 va[2];
#pragma unroll
            for (int j = 0; j < 2; ++j) {
                int i   = tid + j * 256;
                int row = i >> 2;
                int cq  = (i & 3) << 2;
                int idx = sI[row];
                float4 v = __ldg((const float4*)(Fin + (size_t)idx * CIN + (c0 + cq)));
                if (FUSE) {
                    v.x = fmaf(lrelu(v.x), sSc[c0 + cq + 0], sSh[c0 + cq + 0]);
                    v.y = fmaf(lrelu(v.y), sSc[c0 + cq + 1], sSh[c0 + cq + 1]);
                    v.z = fmaf(lrelu(v.z), sSc[c0 + cq + 2], sSh[c0 + cq + 2]);
                    v.w = fmaf(lrelu(v.w), sSc[c0 + cq + 3], sSh[c0 + cq + 3]);
                }
                va[j] = v;
            }
            float4 vb[2];
#pragma unroll
            for (int j = 0; j < 2; ++j) {
                int i  = tid + j * 256;
                int kk = i >> 5;
                int c4 = (i & 31) << 2;
                vb[j]  = __ldg((const float4*)(Wk + (size_t)(c0 + kk) * CO + c4));
            }
            __syncthreads();
#pragma unroll
            for (int j = 0; j < 2; ++j) {
                int i   = tid + j * 256;
                int row = i >> 2;
                int cq  = (i & 3) << 2;
                As[cq + 0][row] = va[j].x;
                As[cq + 1][row] = va[j].y;
                As[cq + 2][row] = va[j].z;
                As[cq + 3][row] = va[j].w;
                int kk = i >> 5;
                int c4 = (i & 31) << 2;
                *(float4*)&Bs[kk][c4] = vb[j];
            }
            __syncthreads();
#pragma unroll
            for (int kk = 0; kk < TK; ++kk) {
                float4 a0 = *(const float4*)&As[kk][trow * 4];
                float4 a1 = *(const float4*)&As[kk][64 + trow * 4];
                ulonglong2 b0 = *(const ulonglong2*)&Bs[kk][tcol * 4];
                ulonglong2 b1 = *(const ulonglong2*)&Bs[kk][64 + tcol * 4];
                unsigned long long ap[8] = {pack2(a0.x), pack2(a0.y), pack2(a0.z), pack2(a0.w),
                                            pack2(a1.x), pack2(a1.y), pack2(a1.z), pack2(a1.w)};
                unsigned long long bp[4] = {b0.x, b0.y, b1.x, b1.y};
#pragma unroll
                for (int r = 0; r < 8; ++r)
#pragma unroll
                    for (int p = 0; p < 4; ++p) fma2(acc[r][p], ap[r], bp[p]);
            }
        }

#pragma unroll
        for (int r = 0; r < 8; ++r) {
            int lr = (r < 4) ? (trow * 4 + r) : (64 + trow * 4 + (r - 4));
            int m  = sM[lr];
            if (m >= 0) {
                float v[8];
#pragma unroll
                for (int p = 0; p < 4; ++p) unpack2(acc[r][p], v[2 * p], v[2 * p + 1]);
                float* orow = Out + (size_t)m * CO;
                redadd4(orow + tcol * 4,      v[0], v[1], v[2], v[3]);
                redadd4(orow + 64 + tcol * 4, v[4], v[5], v[6], v[7]);
            }
        }
    }
}

// ---------------------------------------------------------------------------
// BN stats on raw conv output (applies lrelu): per-block partial sum/sumsq.
// ---------------------------------------------------------------------------
__global__ void stats_kernel(const float* __restrict__ Y, int N, float* __restrict__ part) {
    int c    = threadIdx.x & 127;
    int half = threadIdx.x >> 7;
    int rows = (N + gridDim.x - 1) / gridDim.x;
    int r0   = blockIdx.x * rows;
    int r1   = min(N, r0 + rows);
    float s = 0.f, q = 0.f;
    for (int r = r0 + half; r < r1; r += 2) {
        float x = lrelu(__ldg(&Y[(size_t)r * 128 + c]));
        s += x; q += x * x;
    }
    __shared__ float sh[256];
    sh[threadIdx.x] = s; __syncthreads();
    if (half == 0) part[(size_t)blockIdx.x * 256 + c] = sh[c] + sh[128 + c];
    __syncthreads();
    sh[threadIdx.x] = q; __syncthreads();
    if (half == 0) part[(size_t)blockIdx.x * 256 + 128 + c] = sh[c] + sh[128 + c];
}

__global__ void reduce1_kernel(const float* __restrict__ part, int nb,
                               float* __restrict__ part2) {
    int rpb = (nb + 63) >> 6;
    int r0  = blockIdx.x * rpb;
    int r1  = min(nb, r0 + rpb);
    float s = 0.f;
    for (int r = r0; r < r1; ++r) s += part[(size_t)r * 256 + threadIdx.x];
    part2[blockIdx.x * 256 + threadIdx.x] = s;
}

__global__ void reduce2_kernel(const float* __restrict__ part2, float invn,
                               const float* __restrict__ g, const float* __restrict__ b,
                               float* __restrict__ scale, float* __restrict__ shift) {
    int c = threadIdx.x;
    float s = 0.f, q = 0.f;
#pragma unroll
    for (int j = 0; j < 64; ++j) {
        s += part2[j * 256 + c];
        q += part2[j * 256 + 128 + c];
    }
    float mean = s * invn;
    float var  = q * invn - mean * mean;
    float sc   = g[c] * rsqrtf(var + 1e-5f);
    scale[c] = sc;
    shift[c] = b[c] - mean * sc;
}

// resA = BN3(lrelu(y4)) + BN1(lrelu(y2))
__global__ void add_bn_kernel(const float* __restrict__ y4, const float* __restrict__ y2,
                              const float* __restrict__ sc4, const float* __restrict__ sh4,
                              const float* __restrict__ sc2, const float* __restrict__ sh2,
                              float* __restrict__ out, int n4) {
    int i = blockIdx.x * blockDim.x + threadIdx.x;
    if (i >= n4) return;
    int cg = i & 31;
    float4 a  = __ldg((const float4*)y4 + i);
    float4 c  = __ldg((const float4*)y2 + i);
    float4 s4 = __ldg((const float4*)sc4 + cg);
    float4 h4 = __ldg((const float4*)sh4 + cg);
    float4 s2 = __ldg((const float4*)sc2 + cg);
    float4 h2 = __ldg((const float4*)sh2 + cg);
    float4 o;
    o.x = fmaf(lrelu(a.x), s4.x, h4.x) + fmaf(lrelu(c.x), s2.x, h2.x);
    o.y = fmaf(lrelu(a.y), s4.y, h4.y) + fmaf(lrelu(c.y), s2.y, h2.y);
    o.z = fmaf(lrelu(a.z), s4.z, h4.z) + fmaf(lrelu(c.z), s2.z, h2.z);
    o.w = fmaf(lrelu(a.w), s4.w, h4.w) + fmaf(lrelu(c.w), s2.w, h2.w);
    ((float4*)out)[i] = o;
}

extern "C" void kernel_launch(void* const* d_in, const int* in_sizes, int n_in,
                              void* d_out, int out_size) {
    const float* feats = (const float*)d_in[0];
    const int*   map31 = (const int*)d_in[1];
    const int*   map13 = (const int*)d_in[2];
    const int*   mpool = (const int*)d_in[3];
    const float* W1    = (const float*)d_in[4];
    const float* W1_2  = (const float*)d_in[5];
    const float* W2    = (const float*)d_in[6];
    const float* W3    = (const float*)d_in[7];
    const float* Wp    = (const float*)d_in[8];
    const float* g0    = (const float*)d_in[9];
    const float* b0    = (const float*)d_in[10];
    const float* g0_2  = (const float*)d_in[11];
    const float* b0_2  = (const float*)d_in[12];
    const float* g1    = (const float*)d_in[13];
    const float* b1    = (const float*)d_in[14];
    const float* g2    = (const float*)d_in[15];
    const float* b2    = (const float*)d_in[16];

    int N = in_sizes[0] / 64;
    int M = in_sizes[3] / 27;

    float *Y1, *Y2, *Y4, *part, *part2, *scaleA, *shiftA;
    int2 *p31, *p13, *pP;
    int  *cnt, *dTap, *dBase, *nt;
    cudaGetSymbolAddress((void**)&Y1, g_Y1);
    cudaGetSymbolAddress((void**)&Y2, g_Y2);
    cudaGetSymbolAddress((void**)&Y4, g_Y4);
    cudaGetSymbolAddress((void**)&part, g_part);
    cudaGetSymbolAddress((void**)&part2, g_part2);
    cudaGetSymbolAddress((void**)&scaleA, g_scale);
    cudaGetSymbolAddress((void**)&shiftA, g_shift);
    cudaGetSymbolAddress((void**)&p31, g_pairs31);
    cudaGetSymbolAddress((void**)&p13, g_pairs13);
    cudaGetSymbolAddress((void**)&pP,  g_pairsP);
    cudaGetSymbolAddress((void**)&cnt, g_cnt);
    cudaGetSymbolAddress((void**)&dTap, g_dirTap);
    cudaGetSymbolAddress((void**)&dBase, g_dirBase);
    cudaGetSymbolAddress((void**)&nt, g_nt);

    float* resB = (float*)d_out;
    float* resA = (float*)d_out + (size_t)M * CO;

    int nb = (N + TM - 1) / TM;
    float invn = 1.0f / (float)N;

    // tile directory regions: map31 at 0, map13 at 20000, pool at 40000
    int* dTap31 = dTap;          int* dBase31 = dBase;
    int* dTap13 = dTap + 20000;  int* dBase13 = dBase + 20000;
    int* dTapP  = dTap + 40000;  int* dBaseP  = dBase + 40000;

    // ---- one-time compaction of the three maps ----
    cudaMemsetAsync(cnt, 0, 64 * sizeof(int));
    compact_kernel<<<(9 * N + 255) / 256, 256>>>(map31, 9, N, 4, p31, N, cnt);
    compact_kernel<<<(9 * N + 255) / 256, 256>>>(map13, 9, N, 4, p13, N, cnt + 16);
    compact_kernel<<<(27 * M + 255) / 256, 256>>>(mpool, 27, M, -1, pP, M, cnt + 32);
    pad_kernel<<<9, 128>>>(cnt, p31, N);
    pad_kernel<<<9, 128>>>(cnt + 16, p13, N);
    pad_kernel<<<27, 128>>>(cnt + 32, pP, M);
    build_dir_kernel<<<1, 256>>>(cnt, 9, N, dTap31, dBase31, nt + 0);
    build_dir_kernel<<<1, 256>>>(cnt + 16, 9, N, dTap13, dBase13, nt + 1);
    build_dir_kernel<<<1, 256>>>(cnt + 32, 27, M, dTapP, dBaseP, nt + 2);

    // ---- conv1 (3,1,3): feats -> Y1 (raw) ----
    center_kernel<64, false><<<nb, 256>>>(feats, W1 + (size_t)4 * 64 * CO, N,
                                          nullptr, nullptr, Y1);
    scatter_kernel<64, false><<<SCATTER_GRID, 256>>>(feats, W1, dTap31, dBase31, nt + 0,
                                                     p31, nullptr, nullptr, Y1);
    stats_kernel<<<STATS_GB, 256>>>(Y1, N, part);
    reduce1_kernel<<<64, 256>>>(part, STATS_GB, part2);
    reduce2_kernel<<<1, 128>>>(part2, invn, g0, b0, scaleA + 0, shiftA + 0);

    // ---- conv1_2 (1,3,3): BN0(lrelu(Y1)) -> Y2 (raw) ----
    center_kernel<128, true><<<nb, 256>>>(Y1, W1_2 + (size_t)4 * 128 * CO, N,
                                          scaleA + 0, shiftA + 0, Y2);
    scatter_kernel<128, true><<<SCATTER_GRID, 256>>>(Y1, W1_2, dTap13, dBase13, nt + 1,
                                                     p13, scaleA + 0, shiftA + 0, Y2);
    stats_kernel<<<STATS_GB, 256>>>(Y2, N, part);
    reduce1_kernel<<<64, 256>>>(part, STATS_GB, part2);
    reduce2_kernel<<<1, 128>>>(part2, invn, g0_2, b0_2, scaleA + 128, shiftA + 128);

    // ---- conv2 (1,3,3): feats -> Y3 (reuse Y1) ----
    center_kernel<64, false><<<nb, 256>>>(feats, W2 + (size_t)4 * 64 * CO, N,
                                          nullptr, nullptr, Y1);
    scatter_kernel<64, false><<<SCATTER_GRID, 256>>>(feats, W2, dTap13, dBase13, nt + 1,
                                                     p13, nullptr, nullptr, Y1);
    stats_kernel<<<STATS_GB, 256>>>(Y1, N, part);
    reduce1_kernel<<<64, 256>>>(part, STATS_GB, part2);
    reduce2_kernel<<<1, 128>>>(part2, invn, g1, b1, scaleA + 256, shiftA + 256);

    // ---- conv3 (3,1,3): BN2(lrelu(Y3)) -> Y4 (raw) ----
    center_kernel<128, true><<<nb, 256>>>(Y1, W3 + (size_t)4 * 128 * CO, N,
                                          scaleA + 256, shiftA + 256, Y4);
    scatter_kernel<128, true><<<SCATTER_GRID, 256>>>(Y1, W3, dTap31, dBase31, nt + 0,
                                                     p31, scaleA + 256, shiftA + 256, Y4);
    stats_kernel<<<STATS_GB, 256>>>(Y4, N, part);
    reduce1_kernel<<<64, 256>>>(part, STATS_GB, part2);
    reduce2_kernel<<<1, 128>>>(part2, invn, g2, b2, scaleA + 384, shiftA + 384);

    // ---- resA = BN3(lrelu(Y4)) + BN1(lrelu(Y2)) ----
    int n4 = N * (CO / 4);
    add_bn_kernel<<<(n4 + 255) / 256, 256>>>(Y4, Y2, scaleA + 384, shiftA + 384,
                                             scaleA + 128, shiftA + 128, resA, n4);

    // ---- pool conv (3,3,3)/(2,2,1): resA -> resB ----
    cudaMemsetAsync(resB, 0, (size_t)M * CO * sizeof(float));
    scatter_kernel<128, false><<<SCATTER_GRID, 256>>>(resA, Wp, dTapP, dBaseP, nt + 2,
                                                      pP, nullptr, nullptr, resB);
}

// round 5
// speedup vs baseline: 5.1513x; 1.2324x over previous
#include <cuda_runtime.h>
#include <cstdint>

// ---------------------------------------------------------------------------
// ResBlock sparse-conv, round 5: TF32 mma.sync (legacy HMMA path — tcgen05 is
// rejected by this toolchain's ptxas target). Same pipeline as round 2:
//   dense center-tap GEMM + compacted per-tap scatter-GEMM (red.global.add)
//   + separate BN-stats passes; lrelu+BN fused into consumer gathers.
// Inner core: 128x128 block, 8 warps (2x4), each warp 64x32 via m16n8k8 tf32.
// ---------------------------------------------------------------------------

constexpr int CO   = 128;
constexpr int TM   = 128;
constexpr int TK   = 16;
constexpr int MAXN = 300000;
constexpr int STATS_GB = 2048;
constexpr int SCATTER_GRID = 296;

__device__ float g_Y1[(size_t)MAXN * CO];
__device__ float g_Y2[(size_t)MAXN * CO];
__device__ float g_Y4[(size_t)MAXN * CO];
__device__ float g_part[(size_t)STATS_GB * 256];
__device__ float g_part2[64 * 256];
__device__ float g_scale[4 * CO];
__device__ float g_shift[4 * CO];

__device__ int2 g_pairs31[(size_t)9 * MAXN];
__device__ int2 g_pairs13[(size_t)9 * MAXN];
__device__ int2 g_pairsP[(size_t)27 * MAXN];
__device__ int  g_cnt[64];
__device__ int  g_dirTap[110000];
__device__ int  g_dirBase[110000];
__device__ int  g_nt[4];

// ---------------- helpers ----------------
__device__ __forceinline__ uint32_t tf32r(float x) {
    uint32_t u;
    asm("cvt.rna.tf32.f32 %0, %1;" : "=r"(u) : "f"(x));
    return u;
}
__device__ __forceinline__ void mma16n8k8(float* c, const uint32_t* a, const uint32_t* b) {
    asm volatile("mma.sync.aligned.m16n8k8.row.col.f32.tf32.tf32.f32 "
                 "{%0,%1,%2,%3}, {%4,%5,%6,%7}, {%8,%9}, {%0,%1,%2,%3};"
                 : "+f"(c[0]), "+f"(c[1]), "+f"(c[2]), "+f"(c[3])
                 : "r"(a[0]), "r"(a[1]), "r"(a[2]), "r"(a[3]), "r"(b[0]), "r"(b[1]));
}
__device__ __forceinline__ void redadd2(float* p, float a, float b) {
    asm volatile("red.global.add.v2.f32 [%0], {%1,%2};"
                 :: "l"(p), "f"(a), "f"(b) : "memory");
}
__device__ __forceinline__ float lrelu(float x) { return (x >= 0.f) ? x : 0.01f * x; }

constexpr int APAD = 132;   // padded row stride (words) for As/Bs

// ---------------------------------------------------------------------------
// Compaction
// ---------------------------------------------------------------------------
__global__ void compact_kernel(const int* __restrict__ kmap, int K, int M, int center,
                               int2* __restrict__ pairs, int cap, int* __restrict__ cnt) {
    int i = blockIdx.x * 256 + threadIdx.x;
    if (i >= K * M) return;
    int k = i / M;
    if (k == center) return;
    int idx = kmap[i];
    if (idx >= 0) {
        int pos = atomicAdd(&cnt[k], 1);
        pairs[(size_t)k * cap + pos] = make_int2(i - k * M, idx);
    }
}

__global__ void pad_kernel(const int* __restrict__ cnt, int2* __restrict__ pairs, int cap) {
    int k = blockIdx.x;
    int c = cnt[k];
    int e = ((c + TM - 1) / TM) * TM;
    for (int j = c + threadIdx.x; j < e; j += blockDim.x)
        pairs[(size_t)k * cap + j] = make_int2(-1, 0);
}

__global__ void build_dir_kernel(const int* __restrict__ cnt, int K, int cap,
                                 int* __restrict__ tileTap, int* __restrict__ tileBase,
                                 int* __restrict__ ntOut) {
    __shared__ int ntk[32], off[32];
    if (threadIdx.x == 0) {
        int t = 0;
        for (int k = 0; k < K; ++k) {
            off[k] = t;
            ntk[k] = (cnt[k] + TM - 1) / TM;
            t += ntk[k];
        }
        *ntOut = t;
    }
    __syncthreads();
    for (int k = 0; k < K; ++k)
        for (int j = threadIdx.x; j < ntk[k]; j += blockDim.x) {
            tileTap[off[k] + j]  = k;
            tileBase[off[k] + j] = k * cap + j * TM;
        }
}

// ---------------------------------------------------------------------------
// Shared MMA core (warp 64x32 of a 128x128 tile, m16n8k8 tf32)
//   As[k][m] / Bs[k][n] padded to APAD words per row, tf32-converted values.
// ---------------------------------------------------------------------------
struct Frag { float acc[4][4][4]; };

__device__ __forceinline__ void core_init(Frag& f) {
#pragma unroll
    for (int ma = 0; ma < 4; ++ma)
#pragma unroll
        for (int na = 0; na < 4; ++na)
#pragma unroll
            for (int p = 0; p < 4; ++p) f.acc[ma][na][p] = 0.f;
}

__device__ __forceinline__ void core_compute(Frag& f, const uint32_t* As, const uint32_t* Bs,
                                             int mb, int nb, int lane) {
    const int l3 = lane & 3, l2 = lane >> 2;
#pragma unroll
    for (int ks = 0; ks < TK; ks += 8) {
        uint32_t bf[4][2];
#pragma unroll
        for (int na = 0; na < 4; ++na) {
            bf[na][0] = Bs[(ks + l3) * APAD + nb + na * 8 + l2];
            bf[na][1] = Bs[(ks + 4 + l3) * APAD + nb + na * 8 + l2];
        }
#pragma unroll
        for (int ma = 0; ma < 4; ++ma) {
            const int mrow = mb + ma * 16 + l2;
            uint32_t af[4];
            af[0] = As[(ks + l3) * APAD + mrow];
            af[1] = As[(ks + l3) * APAD + mrow + 8];
            af[2] = As[(ks + 4 + l3) * APAD + mrow];
            af[3] = As[(ks + 4 + l3) * APAD + mrow + 8];
#pragma unroll
            for (int na = 0; na < 4; ++na) mma16n8k8(f.acc[ma][na], af, bf[na]);
        }
    }
}

// ---------------------------------------------------------------------------
// Dense center-tap GEMM: Out[m] = T(Fin[m]) @ Wc   (T = lrelu+BN if FUSE)
// ---------------------------------------------------------------------------
template<int CIN, bool FUSE>
__global__ void __launch_bounds__(256, 2) center_kernel(
    const float* __restrict__ Fin, const float* __restrict__ Wc, int M,
    const float* __restrict__ inScale, const float* __restrict__ inShift,
    float* __restrict__ Out)
{
    __shared__ uint32_t As[TK * APAD];
    __shared__ uint32_t Bs[TK * APAD];
    __shared__ float sSc[128], sSh[128];

    const int tid  = threadIdx.x;
    const int m0   = blockIdx.x * TM;
    const int wid  = tid >> 5, lane = tid & 31;
    const int mb   = (wid & 1) * 64, nb = (wid >> 1) * 32;

    if (FUSE && tid < CIN) { sSc[tid] = inScale[tid]; sSh[tid] = inShift[tid]; }
    __syncthreads();

    Frag f;
    core_init(f);

#pragma unroll 1
    for (int c0 = 0; c0 < CIN; c0 += TK) {
        float4 va[2];
#pragma unroll
        for (int j = 0; j < 2; ++j) {
            int i   = tid + j * 256;
            int row = i >> 2;
            int cq  = (i & 3) << 2;
            int m   = m0 + row;
            float4 v = make_float4(0.f, 0.f, 0.f, 0.f);
            if (m < M) {
                v = __ldg((const float4*)(Fin + (size_t)m * CIN + (c0 + cq)));
                if (FUSE) {
                    v.x = fmaf(lrelu(v.x), sSc[c0 + cq + 0], sSh[c0 + cq + 0]);
                    v.y = fmaf(lrelu(v.y), sSc[c0 + cq + 1], sSh[c0 + cq + 1]);
                    v.z = fmaf(lrelu(v.z), sSc[c0 + cq + 2], sSh[c0 + cq + 2]);
                    v.w = fmaf(lrelu(v.w), sSc[c0 + cq + 3], sSh[c0 + cq + 3]);
                }
            }
            va[j] = v;
        }
        float4 vb[2];
#pragma unroll
        for (int j = 0; j < 2; ++j) {
            int i  = tid + j * 256;
            int kk = i >> 5;
            int c4 = (i & 31) << 2;
            vb[j]  = __ldg((const float4*)(Wc + (size_t)(c0 + kk) * CO + c4));
        }
        __syncthreads();
#pragma unroll
        for (int j = 0; j < 2; ++j) {
            int i   = tid + j * 256;
            int row = i >> 2;
            int cq  = (i & 3) << 2;
            As[(cq + 0) * APAD + row] = tf32r(va[j].x);
            As[(cq + 1) * APAD + row] = tf32r(va[j].y);
            As[(cq + 2) * APAD + row] = tf32r(va[j].z);
            As[(cq + 3) * APAD + row] = tf32r(va[j].w);
            int kk = i >> 5;
            int c4 = (i & 31) << 2;
            uint4 q;
            q.x = tf32r(vb[j].x); q.y = tf32r(vb[j].y);
            q.z = tf32r(vb[j].z); q.w = tf32r(vb[j].w);
            *(uint4*)&Bs[kk * APAD + c4] = q;
        }
        __syncthreads();
        core_compute(f, As, Bs, mb, nb, lane);
        __syncthreads();
    }

    const int l3 = lane & 3, l2 = lane >> 2;
#pragma unroll
    for (int ma = 0; ma < 4; ++ma) {
        int r0 = m0 + mb + ma * 16 + l2;
        int r1 = r0 + 8;
#pragma unroll
        for (int na = 0; na < 4; ++na) {
            int col = nb + na * 8 + 2 * l3;
            if (r0 < M)
                *(float2*)&Out[(size_t)r0 * CO + col] = make_float2(f.acc[ma][na][0], f.acc[ma][na][1]);
            if (r1 < M)
                *(float2*)&Out[(size_t)r1 * CO + col] = make_float2(f.acc[ma][na][2], f.acc[ma][na][3]);
        }
    }
}

// ---------------------------------------------------------------------------
// Scatter-GEMM over compacted tap tiles; epilogue = red.global.add.v2.f32
// ---------------------------------------------------------------------------
template<int CIN, bool FUSE>
__global__ void __launch_bounds__(256, 2) scatter_kernel(
    const float* __restrict__ Fin, const float* __restrict__ W,
    const int* __restrict__ tileTap, const int* __restrict__ tileBase,
    const int* __restrict__ ntPtr, const int2* __restrict__ pairs,
    const float* __restrict__ inScale, const float* __restrict__ inShift,
    float* __restrict__ Out)
{
    __shared__ uint32_t As[TK * APAD];
    __shared__ uint32_t Bs[TK * APAD];
    __shared__ int   sM[TM], sI[TM];
    __shared__ float sSc[128], sSh[128];

    const int tid  = threadIdx.x;
    const int wid  = tid >> 5, lane = tid & 31;
    const int mb   = (wid & 1) * 64, nb = (wid >> 1) * 32;
    const int l3   = lane & 3, l2 = lane >> 2;

    if (FUSE && tid < CIN) { sSc[tid] = inScale[tid]; sSh[tid] = inShift[tid]; }
    const int nTiles = __ldg(ntPtr);

    for (int t = blockIdx.x; t < nTiles; t += gridDim.x) {
        __syncthreads();
        const int k    = tileTap[t];
        const int base = tileBase[t];
        if (tid < TM) {
            int2 pr = pairs[(size_t)base + tid];
            sM[tid] = pr.x;
            sI[tid] = pr.y;
        }
        __syncthreads();
        const float* Wk = W + (size_t)k * CIN * CO;

        Frag f;
        core_init(f);

#pragma unroll 1
        for (int c0 = 0; c0 < CIN; c0 += TK) {
            float4 va[2];
#pragma unroll
            for (int j = 0; j < 2; ++j) {
                int i   = tid + j * 256;
                int row = i >> 2;
                int cq  = (i & 3) << 2;
                int idx = sI[row];
                float4 v = __ldg((const float4*)(Fin + (size_t)idx * CIN + (c0 + cq)));
                if (FUSE) {
                    v.x = fmaf(lrelu(v.x), sSc[c0 + cq + 0], sSh[c0 + cq + 0]);
                    v.y = fmaf(lrelu(v.y), sSc[c0 + cq + 1], sSh[c0 + cq + 1]);
                    v.z = fmaf(lrelu(v.z), sSc[c0 + cq + 2], sSh[c0 + cq + 2]);
                    v.w = fmaf(lrelu(v.w), sSc[c0 + cq + 3], sSh[c0 + cq + 3]);
                }
                va[j] = v;
            }
            float4 vb[2];
#pragma unroll
            for (int j = 0; j < 2; ++j) {
                int i  = tid + j * 256;
                int kk = i >> 5;
                int c4 = (i & 31) << 2;
                vb[j]  = __ldg((const float4*)(Wk + (size_t)(c0 + kk) * CO + c4));
            }
            __syncthreads();
#pragma unroll
            for (int j = 0; j < 2; ++j) {
                int i   = tid + j * 256;
                int row = i >> 2;
                int cq  = (i & 3) << 2;
                As[(cq + 0) * APAD + row] = tf32r(va[j].x);
                As[(cq + 1) * APAD + row] = tf32r(va[j].y);
                As[(cq + 2) * APAD + row] = tf32r(va[j].z);
                As[(cq + 3) * APAD + row] = tf32r(va[j].w);
                int kk = i >> 5;
                int c4 = (i & 31) << 2;
                uint4 q;
                q.x = tf32r(vb[j].x); q.y = tf32r(vb[j].y);
                q.z = tf32r(vb[j].z); q.w = tf32r(vb[j].w);
                *(uint4*)&Bs[kk * APAD + c4] = q;
            }
            __syncthreads();
            core_compute(f, As, Bs, mb, nb, lane);
        }

#pragma unroll
        for (int ma = 0; ma < 4; ++ma) {
            int lr0 = mb + ma * 16 + l2;
            int m0r = sM[lr0];
            int m1r = sM[lr0 + 8];
#pragma unroll
            for (int na = 0; na < 4; ++na) {
                int col = nb + na * 8 + 2 * l3;
                if (m0r >= 0) redadd2(Out + (size_t)m0r * CO + col, f.acc[ma][na][0], f.acc[ma][na][1]);
                if (m1r >= 0) redadd2(Out + (size_t)m1r * CO + col, f.acc[ma][na][2], f.acc[ma][na][3]);
            }
        }
    }
}

// ---------------------------------------------------------------------------
// BN stats on raw conv output (applies lrelu)
// ---------------------------------------------------------------------------
__global__ void stats_kernel(const float* __restrict__ Y, int N, float* __restrict__ part) {
    int c    = threadIdx.x & 127;
    int half = threadIdx.x >> 7;
    int rows = (N + gridDim.x - 1) / gridDim.x;
    int r0   = blockIdx.x * rows;
    int r1   = min(N, r0 + rows);
    float s = 0.f, q = 0.f;
    for (int r = r0 + half; r < r1; r += 2) {
        float x = lrelu(__ldg(&Y[(size_t)r * 128 + c]));
        s += x; q += x * x;
    }
    __shared__ float sh[256];
    sh[threadIdx.x] = s; __syncthreads();
    if (half == 0) part[(size_t)blockIdx.x * 256 + c] = sh[c] + sh[128 + c];
    __syncthreads();
    sh[threadIdx.x] = q; __syncthreads();
    if (half == 0) part[(size_t)blockIdx.x * 256 + 128 + c] = sh[c] + sh[128 + c];
}

__global__ void reduce1_kernel(const float* __restrict__ part, int nb,
                               float* __restrict__ part2) {
    int rpb = (nb + 63) >> 6;
    int r0  = blockIdx.x * rpb;
    int r1  = min(nb, r0 + rpb);
    float s = 0.f;
    for (int r = r0; r < r1; ++r) s += part[(size_t)r * 256 + threadIdx.x];
    part2[blockIdx.x * 256 + threadIdx.x] = s;
}

__global__ void reduce2_kernel(const float* __restrict__ part2, float invn,
                               const float* __restrict__ g, const float* __restrict__ b,
                               float* __restrict__ scale, float* __restrict__ shift) {
    int c = threadIdx.x;
    float s = 0.f, q = 0.f;
#pragma unroll
    for (int j = 0; j < 64; ++j) {
        s += part2[j * 256 + c];
        q += part2[j * 256 + 128 + c];
    }
    float mean = s * invn;
    float var  = q * invn - mean * mean;
    float sc   = g[c] * rsqrtf(var + 1e-5f);
    scale[c] = sc;
    shift[c] = b[c] - mean * sc;
}

__global__ void add_bn_kernel(const float* __restrict__ y4, const float* __restrict__ y2,
                              const float* __restrict__ sc4, const float* __restrict__ sh4,
                              const float* __restrict__ sc2, const float* __restrict__ sh2,
                              float* __restrict__ out, int n4) {
    int i = blockIdx.x * blockDim.x + threadIdx.x;
    if (i >= n4) return;
    int cg = i & 31;
    float4 a  = __ldg((const float4*)y4 + i);
    float4 c  = __ldg((const float4*)y2 + i);
    float4 s4 = __ldg((const float4*)sc4 + cg);
    float4 h4 = __ldg((const float4*)sh4 + cg);
    float4 s2 = __ldg((const float4*)sc2 + cg);
    float4 h2 = __ldg((const float4*)sh2 + cg);
    float4 o;
    o.x = fmaf(lrelu(a.x), s4.x, h4.x) + fmaf(lrelu(c.x), s2.x, h2.x);
    o.y = fmaf(lrelu(a.y), s4.y, h4.y) + fmaf(lrelu(c.y), s2.y, h2.y);
    o.z = fmaf(lrelu(a.z), s4.z, h4.z) + fmaf(lrelu(c.z), s2.z, h2.z);
    o.w = fmaf(lrelu(a.w), s4.w, h4.w) + fmaf(lrelu(c.w), s2.w, h2.w);
    ((float4*)out)[i] = o;
}

extern "C" void kernel_launch(void* const* d_in, const int* in_sizes, int n_in,
                              void* d_out, int out_size) {
    const float* feats = (const float*)d_in[0];
    const int*   map31 = (const int*)d_in[1];
    const int*   map13 = (const int*)d_in[2];
    const int*   mpool = (const int*)d_in[3];
    const float* W1    = (const float*)d_in[4];
    const float* W1_2  = (const float*)d_in[5];
    const float* W2    = (const float*)d_in[6];
    const float* W3    = (const float*)d_in[7];
    const float* Wp    = (const float*)d_in[8];
    const float* g0    = (const float*)d_in[9];
    const float* b0    = (const float*)d_in[10];
    const float* g0_2  = (const float*)d_in[11];
    const float* b0_2  = (const float*)d_in[12];
    const float* g1    = (const float*)d_in[13];
    const float* b1    = (const float*)d_in[14];
    const float* g2    = (const float*)d_in[15];
    const float* b2    = (const float*)d_in[16];

    int N = in_sizes[0] / 64;
    int M = in_sizes[3] / 27;

    float *Y1, *Y2, *Y4, *part, *part2, *scaleA, *shiftA;
    int2 *p31, *p13, *pP;
    int  *cnt, *dTap, *dBase, *nt;
    cudaGetSymbolAddress((void**)&Y1, g_Y1);
    cudaGetSymbolAddress((void**)&Y2, g_Y2);
    cudaGetSymbolAddress((void**)&Y4, g_Y4);
    cudaGetSymbolAddress((void**)&part, g_part);
    cudaGetSymbolAddress((void**)&part2, g_part2);
    cudaGetSymbolAddress((void**)&scaleA, g_scale);
    cudaGetSymbolAddress((void**)&shiftA, g_shift);
    cudaGetSymbolAddress((void**)&p31, g_pairs31);
    cudaGetSymbolAddress((void**)&p13, g_pairs13);
    cudaGetSymbolAddress((void**)&pP,  g_pairsP);
    cudaGetSymbolAddress((void**)&cnt, g_cnt);
    cudaGetSymbolAddress((void**)&dTap, g_dirTap);
    cudaGetSymbolAddress((void**)&dBase, g_dirBase);
    cudaGetSymbolAddress((void**)&nt, g_nt);

    float* resB = (float*)d_out;
    float* resA = (float*)d_out + (size_t)M * CO;

    int nb = (N + TM - 1) / TM;
    float invn = 1.0f / (float)N;

    int* dTap31 = dTap;          int* dBase31 = dBase;
    int* dTap13 = dTap + 20000;  int* dBase13 = dBase + 20000;
    int* dTapP  = dTap + 40000;  int* dBaseP  = dBase + 40000;

    // ---- one-time compaction of the three maps ----
    cudaMemsetAsync(cnt, 0, 64 * sizeof(int));
    compact_kernel<<<(9 * N + 255) / 256, 256>>>(map31, 9, N, 4, p31, N, cnt);
    compact_kernel<<<(9 * N + 255) / 256, 256>>>(map13, 9, N, 4, p13, N, cnt + 16);
    compact_kernel<<<(27 * M + 255) / 256, 256>>>(mpool, 27, M, -1, pP, M, cnt + 32);
    pad_kernel<<<9, 128>>>(cnt, p31, N);
    pad_kernel<<<9, 128>>>(cnt + 16, p13, N);
    pad_kernel<<<27, 128>>>(cnt + 32, pP, M);
    build_dir_kernel<<<1, 256>>>(cnt, 9, N, dTap31, dBase31, nt + 0);
    build_dir_kernel<<<1, 256>>>(cnt + 16, 9, N, dTap13, dBase13, nt + 1);
    build_dir_kernel<<<1, 256>>>(cnt + 32, 27, M, dTapP, dBaseP, nt + 2);

    // ---- conv1 (3,1,3): feats -> Y1 (raw) ----
    center_kernel<64, false><<<nb, 256>>>(feats, W1 + (size_t)4 * 64 * CO, N,
                                          nullptr, nullptr, Y1);
    scatter_kernel<64, false><<<SCATTER_GRID, 256>>>(feats, W1, dTap31, dBase31, nt + 0,
                                                     p31, nullptr, nullptr, Y1);
    stats_kernel<<<STATS_GB, 256>>>(Y1, N, part);
    reduce1_kernel<<<64, 256>>>(part, STATS_GB, part2);
    reduce2_kernel<<<1, 128>>>(part2, invn, g0, b0, scaleA + 0, shiftA + 0);

    // ---- conv1_2 (1,3,3): BN0(lrelu(Y1)) -> Y2 (raw) ----
    center_kernel<128, true><<<nb, 256>>>(Y1, W1_2 + (size_t)4 * 128 * CO, N,
                                          scaleA + 0, shiftA + 0, Y2);
    scatter_kernel<128, true><<<SCATTER_GRID, 256>>>(Y1, W1_2, dTap13, dBase13, nt + 1,
                                                     p13, scaleA + 0, shiftA + 0, Y2);
    stats_kernel<<<STATS_GB, 256>>>(Y2, N, part);
    reduce1_kernel<<<64, 256>>>(part, STATS_GB, part2);
    reduce2_kernel<<<1, 128>>>(part2, invn, g0_2, b0_2, scaleA + 128, shiftA + 128);

    // ---- conv2 (1,3,3): feats -> Y3 (reuse Y1) ----
    center_kernel<64, false><<<nb, 256>>>(feats, W2 + (size_t)4 * 64 * CO, N,
                                          nullptr, nullptr, Y1);
    scatter_kernel<64, false><<<SCATTER_GRID, 256>>>(feats, W2, dTap13, dBase13, nt + 1,
                                                     p13, nullptr, nullptr, Y1);
    stats_kernel<<<STATS_GB, 256>>>(Y1, N, part);
    reduce1_kernel<<<64, 256>>>(part, STATS_GB, part2);
    reduce2_kernel<<<1, 128>>>(part2, invn, g1, b1, scaleA + 256, shiftA + 256);

    // ---- conv3 (3,1,3): BN2(lrelu(Y3)) -> Y4 (raw) ----
    center_kernel<128, true><<<nb, 256>>>(Y1, W3 + (size_t)4 * 128 * CO, N,
                                          scaleA + 256, shiftA + 256, Y4);
    scatter_kernel<128, true><<<SCATTER_GRID, 256>>>(Y1, W3, dTap31, dBase31, nt + 0,
                                                     p31, scaleA + 256, shiftA + 256, Y4);
    stats_kernel<<<STATS_GB, 256>>>(Y4, N, part);
    reduce1_kernel<<<64, 256>>>(part, STATS_GB, part2);
    reduce2_kernel<<<1, 128>>>(part2, invn, g2, b2, scaleA + 384, shiftA + 384);

    // ---- resA = BN3(lrelu(Y4)) + BN1(lrelu(Y2)) ----
    int n4 = N * (CO / 4);
    add_bn_kernel<<<(n4 + 255) / 256, 256>>>(Y4, Y2, scaleA + 384, shiftA + 384,
                                             scaleA + 128, shiftA + 128, resA, n4);

    // ---- pool conv (3,3,3)/(2,2,1): resA -> resB ----
    cudaMemsetAsync(resB, 0, (size_t)M * CO * sizeof(float));
    scatter_kernel<128, false><<<SCATTER_GRID, 256>>>(resA, Wp, dTapP, dBaseP, nt + 2,
                                                      pP, nullptr, nullptr, resB);
}

// round 6
// speedup vs baseline: 5.5540x; 1.0782x over previous
#include <cuda_runtime.h>
#include <cstdint>

// ---------------------------------------------------------------------------
// ResBlock sparse-conv, round 6: TF32 mma.sync with rebuilt core.
//   A smem [m][k] stride 36 (float4 STS, conflict-free frag LDS)
//   B smem [k][n] stride 136 (conflict-free), weights pre-converted to tf32
//   TK=32 chunks, A-gather register prefetch across compute.
// Pipeline unchanged: dense center GEMM + compacted scatter GEMM (red.add),
// separate BN stats passes, lrelu+BN fused into consumer gathers.
// ---------------------------------------------------------------------------

constexpr int CO   = 128;
constexpr int TM   = 128;
constexpr int TKC  = 32;
constexpr int ASTR = 36;    // A row stride (words): 36 mod 32 = 4 -> conflict-free
constexpr int BSTR = 136;   // B row stride (words): 136 mod 32 = 8 -> conflict-free
constexpr int MAXN = 300000;
constexpr int STATS_GB = 2048;
constexpr int SCATTER_GRID = 296;

__device__ float g_Y1[(size_t)MAXN * CO];
__device__ float g_Y2[(size_t)MAXN * CO];
__device__ float g_Y4[(size_t)MAXN * CO];
__device__ float g_part[(size_t)STATS_GB * 256];
__device__ float g_part2[64 * 256];
__device__ float g_scale[4 * CO];
__device__ float g_shift[4 * CO];

__device__ int2 g_pairs31[(size_t)9 * MAXN];
__device__ int2 g_pairs13[(size_t)9 * MAXN];
__device__ int2 g_pairsP[(size_t)27 * MAXN];
__device__ int  g_cnt[64];
__device__ int  g_dirTap[110000];
__device__ int  g_dirBase[110000];
__device__ int  g_nt[4];
__device__ uint32_t g_Wt[884736];   // all weights, tf32-rounded bits

// ---------------- helpers ----------------
__device__ __forceinline__ uint32_t tf32r(float x) {
    uint32_t u;
    asm("cvt.rna.tf32.f32 %0, %1;" : "=r"(u) : "f"(x));
    return u;
}
__device__ __forceinline__ void mma16n8k8(float* c, const uint32_t* a, const uint32_t* b) {
    asm volatile("mma.sync.aligned.m16n8k8.row.col.f32.tf32.tf32.f32 "
                 "{%0,%1,%2,%3}, {%4,%5,%6,%7}, {%8,%9}, {%0,%1,%2,%3};"
                 : "+f"(c[0]), "+f"(c[1]), "+f"(c[2]), "+f"(c[3])
                 : "r"(a[0]), "r"(a[1]), "r"(a[2]), "r"(a[3]), "r"(b[0]), "r"(b[1]));
}
__device__ __forceinline__ void redadd2(float* p, float a, float b) {
    asm volatile("red.global.add.v2.f32 [%0], {%1,%2};"
                 :: "l"(p), "f"(a), "f"(b) : "memory");
}
__device__ __forceinline__ float lrelu(float x) { return (x >= 0.f) ? x : 0.01f * x; }

// ---------------------------------------------------------------------------
// Weight pre-conversion to tf32 bits (one-time)
// ---------------------------------------------------------------------------
__global__ void cvtw_kernel(const float* __restrict__ w, int n4, uint32_t* __restrict__ out) {
    int i = blockIdx.x * 256 + threadIdx.x;
    if (i >= n4) return;
    float4 v = __ldg((const float4*)w + i);
    uint4 q;
    q.x = tf32r(v.x); q.y = tf32r(v.y); q.z = tf32r(v.z); q.w = tf32r(v.w);
    ((uint4*)out)[i] = q;
}

// ---------------------------------------------------------------------------
// Compaction
// ---------------------------------------------------------------------------
__global__ void compact_kernel(const int* __restrict__ kmap, int K, int M, int center,
                               int2* __restrict__ pairs, int cap, int* __restrict__ cnt) {
    int i = blockIdx.x * 256 + threadIdx.x;
    if (i >= K * M) return;
    int k = i / M;
    if (k == center) return;
    int idx = kmap[i];
    if (idx >= 0) {
        int pos = atomicAdd(&cnt[k], 1);
        pairs[(size_t)k * cap + pos] = make_int2(i - k * M, idx);
    }
}

__global__ void pad_kernel(const int* __restrict__ cnt, int2* __restrict__ pairs, int cap) {
    int k = blockIdx.x;
    int c = cnt[k];
    int e = ((c + TM - 1) / TM) * TM;
    for (int j = c + threadIdx.x; j < e; j += blockDim.x)
        pairs[(size_t)k * cap + j] = make_int2(-1, 0);
}

__global__ void build_dir_kernel(const int* __restrict__ cnt, int K, int cap,
                                 int* __restrict__ tileTap, int* __restrict__ tileBase,
                                 int* __restrict__ ntOut) {
    __shared__ int ntk[32], off[32];
    if (threadIdx.x == 0) {
        int t = 0;
        for (int k = 0; k < K; ++k) {
            off[k] = t;
            ntk[k] = (cnt[k] + TM - 1) / TM;
            t += ntk[k];
        }
        *ntOut = t;
    }
    __syncthreads();
    for (int k = 0; k < K; ++k)
        for (int j = threadIdx.x; j < ntk[k]; j += blockDim.x) {
            tileTap[off[k] + j]  = k;
            tileBase[off[k] + j] = k * cap + j * TM;
        }
}

// ---------------------------------------------------------------------------
// MMA core: warp computes 64x32 of the 128x128 tile over a TK=32 chunk.
// ---------------------------------------------------------------------------
__device__ __forceinline__ void core_compute(float (*acc)[4][4],
                                             const uint32_t* __restrict__ As,
                                             const uint32_t* __restrict__ Bs,
                                             int mb, int nb, int lane) {
    const int l3 = lane & 3, l2 = lane >> 2;
#pragma unroll
    for (int ks = 0; ks < TKC; ks += 8) {
        uint32_t bf[4][2];
#pragma unroll
        for (int na = 0; na < 4; ++na) {
            bf[na][0] = Bs[(ks + l3) * BSTR + nb + na * 8 + l2];
            bf[na][1] = Bs[(ks + 4 + l3) * BSTR + nb + na * 8 + l2];
        }
#pragma unroll
        for (int ma = 0; ma < 4; ++ma) {
            const int mrow = mb + ma * 16 + l2;
            uint32_t af[4];
            af[0] = As[mrow * ASTR + ks + l3];
            af[1] = As[(mrow + 8) * ASTR + ks + l3];
            af[2] = As[mrow * ASTR + ks + 4 + l3];
            af[3] = As[(mrow + 8) * ASTR + ks + 4 + l3];
#pragma unroll
            for (int na = 0; na < 4; ++na) mma16n8k8(acc[ma][na], af, bf[na]);
        }
    }
}

// ---------------------------------------------------------------------------
// Dense center-tap GEMM: Out[m] = T(Fin[m]) @ Wc   (T = lrelu+BN if FUSE)
// ---------------------------------------------------------------------------
template<int CIN, bool FUSE>
__global__ void __launch_bounds__(256, 2) center_kernel(
    const float* __restrict__ Fin, const uint32_t* __restrict__ Wt, int M,
    const float* __restrict__ inScale, const float* __restrict__ inShift,
    float* __restrict__ Out)
{
    __shared__ uint32_t As[TM * ASTR];
    __shared__ uint32_t Bs[TKC * BSTR];
    __shared__ float sSc[128], sSh[128];

    const int tid  = threadIdx.x;
    const int m0   = blockIdx.x * TM;
    const int wid  = tid >> 5, lane = tid & 31;
    const int mb   = (wid & 1) * 64, nb = (wid >> 1) * 32;
    const int row  = tid >> 1, half = tid & 1;   // gather: row 0..127, k-half 0/1
    constexpr int CHUNKS = CIN / TKC;

    if (FUSE && tid < CIN) { sSc[tid] = inScale[tid]; sSh[tid] = inShift[tid]; }
    __syncthreads();

    float acc[4][4][4];
#pragma unroll
    for (int ma = 0; ma < 4; ++ma)
#pragma unroll
        for (int na = 0; na < 4; ++na)
#pragma unroll
            for (int p = 0; p < 4; ++p) acc[ma][na][p] = 0.f;

    const int m = m0 + row;
    float4 va[4];

    // prefetch chunk 0
    {
        const int c0 = 0;
#pragma unroll
        for (int j = 0; j < 4; ++j) {
            float4 v = make_float4(0.f, 0.f, 0.f, 0.f);
            if (m < M) {
                v = __ldg((const float4*)(Fin + (size_t)m * CIN + c0 + half * 16) + j);
                if (FUSE) {
                    int c = c0 + half * 16 + j * 4;
                    v.x = fmaf(lrelu(v.x), sSc[c + 0], sSh[c + 0]);
                    v.y = fmaf(lrelu(v.y), sSc[c + 1], sSh[c + 1]);
                    v.z = fmaf(lrelu(v.z), sSc[c + 2], sSh[c + 2]);
                    v.w = fmaf(lrelu(v.w), sSc[c + 3], sSh[c + 3]);
                }
            }
            va[j] = v;
        }
    }

#pragma unroll 1
    for (int c = 0; c < CHUNKS; ++c) {
        const int c0 = c * TKC;
        __syncthreads();                 // previous compute done
        // store A chunk (float4, conflict-free)
#pragma unroll
        for (int j = 0; j < 4; ++j) {
            uint4 q;
            q.x = tf32r(va[j].x); q.y = tf32r(va[j].y);
            q.z = tf32r(va[j].z); q.w = tf32r(va[j].w);
            *(uint4*)&As[row * ASTR + half * 16 + j * 4] = q;
        }
        // B chunk: plain copy of pre-converted weights
#pragma unroll
        for (int j = 0; j < 4; ++j) {
            int i2 = tid + j * 256;          // 0..1023 = 32 rows x 32 uint4
            int kk = i2 >> 5, c4 = (i2 & 31) << 2;
            uint4 b = __ldg((const uint4*)(Wt + (size_t)(c0 + kk) * CO + c4));
            *(uint4*)&Bs[kk * BSTR + c4] = b;
        }
        __syncthreads();
        // prefetch next chunk
        if (c + 1 < CHUNKS) {
            const int cn = c0 + TKC;
#pragma unroll
            for (int j = 0; j < 4; ++j) {
                float4 v = make_float4(0.f, 0.f, 0.f, 0.f);
                if (m < M) {
                    v = __ldg((const float4*)(Fin + (size_t)m * CIN + cn + half * 16) + j);
                    if (FUSE) {
                        int cc = cn + half * 16 + j * 4;
                        v.x = fmaf(lrelu(v.x), sSc[cc + 0], sSh[cc + 0]);
                        v.y = fmaf(lrelu(v.y), sSc[cc + 1], sSh[cc + 1]);
                        v.z = fmaf(lrelu(v.z), sSc[cc + 2], sSh[cc + 2]);
                        v.w = fmaf(lrelu(v.w), sSc[cc + 3], sSh[cc + 3]);
                    }
                }
                va[j] = v;
            }
        }
        core_compute(acc, As, Bs, mb, nb, lane);
    }

    const int l3 = lane & 3, l2 = lane >> 2;
#pragma unroll
    for (int ma = 0; ma < 4; ++ma) {
        int r0 = m0 + mb + ma * 16 + l2;
        int r1 = r0 + 8;
#pragma unroll
        for (int na = 0; na < 4; ++na) {
            int col = nb + na * 8 + 2 * l3;
            if (r0 < M)
                *(float2*)&Out[(size_t)r0 * CO + col] = make_float2(acc[ma][na][0], acc[ma][na][1]);
            if (r1 < M)
                *(float2*)&Out[(size_t)r1 * CO + col] = make_float2(acc[ma][na][2], acc[ma][na][3]);
        }
    }
}

// ---------------------------------------------------------------------------
// Scatter-GEMM over compacted tap tiles; epilogue = red.global.add.v2.f32
// ---------------------------------------------------------------------------
template<int CIN, bool FUSE>
__global__ void __launch_bounds__(256, 2) scatter_kernel(
    const float* __restrict__ Fin, const uint32_t* __restrict__ Wt,
    const int* __restrict__ tileTap, const int* __restrict__ tileBase,
    const int* __restrict__ ntPtr, const int2* __restrict__ pairs,
    const float* __restrict__ inScale, const float* __restrict__ inShift,
    float* __restrict__ Out)
{
    __shared__ uint32_t As[TM * ASTR];
    __shared__ uint32_t Bs[TKC * BSTR];
    __shared__ int   sM[TM], sI[TM];
    __shared__ float sSc[128], sSh[128];

    const int tid  = threadIdx.x;
    const int wid  = tid >> 5, lane = tid & 31;
    const int mb   = (wid & 1) * 64, nb = (wid >> 1) * 32;
    const int row  = tid >> 1, half = tid & 1;
    const int l3   = lane & 3, l2 = lane >> 2;
    constexpr int CHUNKS = CIN / TKC;

    if (FUSE && tid < CIN) { sSc[tid] = inScale[tid]; sSh[tid] = inShift[tid]; }
    const int nTiles = __ldg(ntPtr);

    for (int t = blockIdx.x; t < nTiles; t += gridDim.x) {
        __syncthreads();                 // prior epilogue read sM; safe to overwrite
        const int k    = __ldg(&tileTap[t]);
        const int base = __ldg(&tileBase[t]);
        if (tid < TM) {
            int2 pr = __ldg(&pairs[(size_t)base + tid]);
            sM[tid] = pr.x;
            sI[tid] = pr.y;
        }
        __syncthreads();
        const uint32_t* Wk = Wt + (size_t)k * CIN * CO;
        const int idx = sI[row];

        float acc[4][4][4];
#pragma unroll
        for (int ma = 0; ma < 4; ++ma)
#pragma unroll
            for (int na = 0; na < 4; ++na)
#pragma unroll
                for (int p = 0; p < 4; ++p) acc[ma][na][p] = 0.f;

        float4 va[4];
        // prefetch chunk 0
#pragma unroll
        for (int j = 0; j < 4; ++j) {
            float4 v = __ldg((const float4*)(Fin + (size_t)idx * CIN + half * 16) + j);
            if (FUSE) {
                int cc = half * 16 + j * 4;
                v.x = fmaf(lrelu(v.x), sSc[cc + 0], sSh[cc + 0]);
                v.y = fmaf(lrelu(v.y), sSc[cc + 1], sSh[cc + 1]);
                v.z = fmaf(lrelu(v.z), sSc[cc + 2], sSh[cc + 2]);
                v.w = fmaf(lrelu(v.w), sSc[cc + 3], sSh[cc + 3]);
            }
            va[j] = v;
        }

#pragma unroll 1
        for (int c = 0; c < CHUNKS; ++c) {
            const int c0 = c * TKC;
            __syncthreads();
#pragma unroll
            for (int j = 0; j < 4; ++j) {
                uint4 q;
                q.x = tf32r(va[j].x); q.y = tf32r(va[j].y);
                q.z = tf32r(va[j].z); q.w = tf32r(va[j].w);
                *(uint4*)&As[row * ASTR + half * 16 + j * 4] = q;
            }
#pragma unroll
            for (int j = 0; j < 4; ++j) {
                int i2 = tid + j * 256;
                int kk = i2 >> 5, c4 = (i2 & 31) << 2;
                uint4 b = __ldg((const uint4*)(Wk + (size_t)(c0 + kk) * CO + c4));
                *(uint4*)&Bs[kk * BSTR + c4] = b;
            }
            __syncthreads();
            if (c + 1 < CHUNKS) {
                const int cn = c0 + TKC;
#pragma unroll
                for (int j = 0; j < 4; ++j) {
                    float4 v = __ldg((const float4*)(Fin + (size_t)idx * CIN + cn + half * 16) + j);
                    if (FUSE) {
                        int cc = cn + half * 16 + j * 4;
                        v.x = fmaf(lrelu(v.x), sSc[cc + 0], sSh[cc + 0]);
                        v.y = fmaf(lrelu(v.y), sSc[cc + 1], sSh[cc + 1]);
                        v.z = fmaf(lrelu(v.z), sSc[cc + 2], sSh[cc + 2]);
                        v.w = fmaf(lrelu(v.w), sSc[cc + 3], sSh[cc + 3]);
                    }
                    va[j] = v;
                }
            }
            core_compute(acc, As, Bs, mb, nb, lane);
        }

#pragma unroll
        for (int ma = 0; ma < 4; ++ma) {
            int lr0 = mb + ma * 16 + l2;
            int m0r = sM[lr0];
            int m1r = sM[lr0 + 8];
#pragma unroll
            for (int na = 0; na < 4; ++na) {
                int col = nb + na * 8 + 2 * l3;
                if (m0r >= 0) redadd2(Out + (size_t)m0r * CO + col, acc[ma][na][0], acc[ma][na][1]);
                if (m1r >= 0) redadd2(Out + (size_t)m1r * CO + col, acc[ma][na][2], acc[ma][na][3]);
            }
        }
    }
}

// ---------------------------------------------------------------------------
// BN stats on raw conv output (applies lrelu)
// ---------------------------------------------------------------------------
__global__ void stats_kernel(const float* __restrict__ Y, int N, float* __restrict__ part) {
    int c    = threadIdx.x & 127;
    int half = threadIdx.x >> 7;
    int rows = (N + gridDim.x - 1) / gridDim.x;
    int r0   = blockIdx.x * rows;
    int r1   = min(N, r0 + rows);
    float s = 0.f, q = 0.f;
    for (int r = r0 + half; r < r1; r += 2) {
        float x = lrelu(__ldg(&Y[(size_t)r * 128 + c]));
        s += x; q += x * x;
    }
    __shared__ float sh[256];
    sh[threadIdx.x] = s; __syncthreads();
    if (half == 0) part[(size_t)blockIdx.x * 256 + c] = sh[c] + sh[128 + c];
    __syncthreads();
    sh[threadIdx.x] = q; __syncthreads();
    if (half == 0) part[(size_t)blockIdx.x * 256 + 128 + c] = sh[c] + sh[128 + c];
}

__global__ void reduce1_kernel(const float* __restrict__ part, int nb,
                               float* __restrict__ part2) {
    int rpb = (nb + 63) >> 6;
    int r0  = blockIdx.x * rpb;
    int r1  = min(nb, r0 + rpb);
    float s = 0.f;
    for (int r = r0; r < r1; ++r) s += part[(size_t)r * 256 + threadIdx.x];
    part2[blockIdx.x * 256 + threadIdx.x] = s;
}

__global__ void reduce2_kernel(const float* __restrict__ part2, float invn,
                               const float* __restrict__ g, const float* __restrict__ b,
                               float* __restrict__ scale, float* __restrict__ shift) {
    int c = threadIdx.x;
    float s = 0.f, q = 0.f;
#pragma unroll
    for (int j = 0; j < 64; ++j) {
        s += part2[j * 256 + c];
        q += part2[j * 256 + 128 + c];
    }
    float mean = s * invn;
    float var  = q * invn - mean * mean;
    float sc   = g[c] * rsqrtf(var + 1e-5f);
    scale[c] = sc;
    shift[c] = b[c] - mean * sc;
}

__global__ void add_bn_kernel(const float* __restrict__ y4, const float* __restrict__ y2,
                              const float* __restrict__ sc4, const float* __restrict__ sh4,
                              const float* __restrict__ sc2, const float* __restrict__ sh2,
                              float* __restrict__ out, int n4) {
    int i = blockIdx.x * blockDim.x + threadIdx.x;
    if (i >= n4) return;
    int cg = i & 31;
    float4 a  = __ldg((const float4*)y4 + i);
    float4 c  = __ldg((const float4*)y2 + i);
    float4 s4 = __ldg((const float4*)sc4 + cg);
    float4 h4 = __ldg((const float4*)sh4 + cg);
    float4 s2 = __ldg((const float4*)sc2 + cg);
    float4 h2 = __ldg((const float4*)sh2 + cg);
    float4 o;
    o.x = fmaf(lrelu(a.x), s4.x, h4.x) + fmaf(lrelu(c.x), s2.x, h2.x);
    o.y = fmaf(lrelu(a.y), s4.y, h4.y) + fmaf(lrelu(c.y), s2.y, h2.y);
    o.z = fmaf(lrelu(a.z), s4.z, h4.z) + fmaf(lrelu(c.z), s2.z, h2.z);
    o.w = fmaf(lrelu(a.w), s4.w, h4.w) + fmaf(lrelu(c.w), s2.w, h2.w);
    ((float4*)out)[i] = o;
}

extern "C" void kernel_launch(void* const* d_in, const int* in_sizes, int n_in,
                              void* d_out, int out_size) {
    const float* feats = (const float*)d_in[0];
    const int*   map31 = (const int*)d_in[1];
    const int*   map13 = (const int*)d_in[2];
    const int*   mpool = (const int*)d_in[3];
    const float* W1    = (const float*)d_in[4];
    const float* W1_2  = (const float*)d_in[5];
    const float* W2    = (const float*)d_in[6];
    const float* W3    = (const float*)d_in[7];
    const float* Wp    = (const float*)d_in[8];
    const float* g0    = (const float*)d_in[9];
    const float* b0    = (const float*)d_in[10];
    const float* g0_2  = (const float*)d_in[11];
    const float* b0_2  = (const float*)d_in[12];
    const float* g1    = (const float*)d_in[13];
    const float* b1    = (const float*)d_in[14];
    const float* g2    = (const float*)d_in[15];
    const float* b2    = (const float*)d_in[16];

    int N = in_sizes[0] / 64;
    int M = in_sizes[3] / 27;

    float *Y1, *Y2, *Y4, *part, *part2, *scaleA, *shiftA;
    int2 *p31, *p13, *pP;
    int  *cnt, *dTap, *dBase, *nt;
    uint32_t* Wt;
    cudaGetSymbolAddress((void**)&Y1, g_Y1);
    cudaGetSymbolAddress((void**)&Y2, g_Y2);
    cudaGetSymbolAddress((void**)&Y4, g_Y4);
    cudaGetSymbolAddress((void**)&part, g_part);
    cudaGetSymbolAddress((void**)&part2, g_part2);
    cudaGetSymbolAddress((void**)&scaleA, g_scale);
    cudaGetSymbolAddress((void**)&shiftA, g_shift);
    cudaGetSymbolAddress((void**)&p31, g_pairs31);
    cudaGetSymbolAddress((void**)&p13, g_pairs13);
    cudaGetSymbolAddress((void**)&pP,  g_pairsP);
    cudaGetSymbolAddress((void**)&cnt, g_cnt);
    cudaGetSymbolAddress((void**)&dTap, g_dirTap);
    cudaGetSymbolAddress((void**)&dBase, g_dirBase);
    cudaGetSymbolAddress((void**)&nt, g_nt);
    cudaGetSymbolAddress((void**)&Wt, g_Wt);

    float* resB = (float*)d_out;
    float* resA = (float*)d_out + (size_t)M * CO;

    int nb = (N + TM - 1) / TM;
    float invn = 1.0f / (float)N;

    int* dTap31 = dTap;          int* dBase31 = dBase;
    int* dTap13 = dTap + 20000;  int* dBase13 = dBase + 20000;
    int* dTapP  = dTap + 40000;  int* dBaseP  = dBase + 40000;

    // pre-converted weight regions (word offsets)
    uint32_t* T1  = Wt;                 // 9*64*128   = 73728
    uint32_t* T12 = Wt + 73728;         // 9*128*128  = 147456
    uint32_t* T2  = Wt + 221184;        // 73728
    uint32_t* T3  = Wt + 294912;        // 147456
    uint32_t* Tp  = Wt + 442368;        // 27*128*128 = 442368
    cvtw_kernel<<<(73728 / 4 + 255) / 256, 256>>>(W1, 73728 / 4, T1);
    cvtw_kernel<<<(147456 / 4 + 255) / 256, 256>>>(W1_2, 147456 / 4, T12);
    cvtw_kernel<<<(73728 / 4 + 255) / 256, 256>>>(W2, 73728 / 4, T2);
    cvtw_kernel<<<(147456 / 4 + 255) / 256, 256>>>(W3, 147456 / 4, T3);
    cvtw_kernel<<<(442368 / 4 + 255) / 256, 256>>>(Wp, 442368 / 4, Tp);

    // ---- one-time compaction of the three maps ----
    cudaMemsetAsync(cnt, 0, 64 * sizeof(int));
    compact_kernel<<<(9 * N + 255) / 256, 256>>>(map31, 9, N, 4, p31, N, cnt);
    compact_kernel<<<(9 * N + 255) / 256, 256>>>(map13, 9, N, 4, p13, N, cnt + 16);
    compact_kernel<<<(27 * M + 255) / 256, 256>>>(mpool, 27, M, -1, pP, M, cnt + 32);
    pad_kernel<<<9, 128>>>(cnt, p31, N);
    pad_kernel<<<9, 128>>>(cnt + 16, p13, N);
    pad_kernel<<<27, 128>>>(cnt + 32, pP, M);
    build_dir_kernel<<<1, 256>>>(cnt, 9, N, dTap31, dBase31, nt + 0);
    build_dir_kernel<<<1, 256>>>(cnt + 16, 9, N, dTap13, dBase13, nt + 1);
    build_dir_kernel<<<1, 256>>>(cnt + 32, 27, M, dTapP, dBaseP, nt + 2);

    // ---- conv1 (3,1,3): feats -> Y1 (raw) ----
    center_kernel<64, false><<<nb, 256>>>(feats, T1 + (size_t)4 * 64 * CO, N,
                                          nullptr, nullptr, Y1);
    scatter_kernel<64, false><<<SCATTER_GRID, 256>>>(feats, T1, dTap31, dBase31, nt + 0,
                                                     p31, nullptr, nullptr, Y1);
    stats_kernel<<<STATS_GB, 256>>>(Y1, N, part);
    reduce1_kernel<<<64, 256>>>(part, STATS_GB, part2);
    reduce2_kernel<<<1, 128>>>(part2, invn, g0, b0, scaleA + 0, shiftA + 0);

    // ---- conv1_2 (1,3,3): BN0(lrelu(Y1)) -> Y2 (raw) ----
    center_kernel<128, true><<<nb, 256>>>(Y1, T12 + (size_t)4 * 128 * CO, N,
                                          scaleA + 0, shiftA + 0, Y2);
    scatter_kernel<128, true><<<SCATTER_GRID, 256>>>(Y1, T12, dTap13, dBase13, nt + 1,
                                                     p13, scaleA + 0, shiftA + 0, Y2);
    stats_kernel<<<STATS_GB, 256>>>(Y2, N, part);
    reduce1_kernel<<<64, 256>>>(part, STATS_GB, part2);
    reduce2_kernel<<<1, 128>>>(part2, invn, g0_2, b0_2, scaleA + 128, shiftA + 128);

    // ---- conv2 (1,3,3): feats -> Y3 (reuse Y1) ----
    center_kernel<64, false><<<nb, 256>>>(feats, T2 + (size_t)4 * 64 * CO, N,
                                          nullptr, nullptr, Y1);
    scatter_kernel<64, false><<<SCATTER_GRID, 256>>>(feats, T2, dTap13, dBase13, nt + 1,
                                                     p13, nullptr, nullptr, Y1);
    stats_kernel<<<STATS_GB, 256>>>(Y1, N, part);
    reduce1_kernel<<<64, 256>>>(part, STATS_GB, part2);
    reduce2_kernel<<<1, 128>>>(part2, invn, g1, b1, scaleA + 256, shiftA + 256);

    // ---- conv3 (3,1,3): BN2(lrelu(Y3)) -> Y4 (raw) ----
    center_kernel<128, true><<<nb, 256>>>(Y1, T3 + (size_t)4 * 128 * CO, N,
                                          scaleA + 256, shiftA + 256, Y4);
    scatter_kernel<128, true><<<SCATTER_GRID, 256>>>(Y1, T3, dTap31, dBase31, nt + 0,
                                                     p31, scaleA + 256, shiftA + 256, Y4);
    stats_kernel<<<STATS_GB, 256>>>(Y4, N, part);
    reduce1_kernel<<<64, 256>>>(part, STATS_GB, part2);
    reduce2_kernel<<<1, 128>>>(part2, invn, g2, b2, scaleA + 384, shiftA + 384);

    // ---- resA = BN3(lrelu(Y4)) + BN1(lrelu(Y2)) ----
    int n4 = N * (CO / 4);
    add_bn_kernel<<<(n4 + 255) / 256, 256>>>(Y4, Y2, scaleA + 384, shiftA + 384,
                                             scaleA + 128, shiftA + 128, resA, n4);

    // ---- pool conv (3,3,3)/(2,2,1): resA -> resB ----
    cudaMemsetAsync(resB, 0, (size_t)M * CO * sizeof(float));
    scatter_kernel<128, false><<<SCATTER_GRID, 256>>>(resA, Tp, dTapP, dBaseP, nt + 2,
                                                      pP, nullptr, nullptr, resB);
}